// round 13
// baseline (speedup 1.0000x reference)
#include <cuda_runtime.h>
#include <math.h>
#include <stdint.h>

#define B_ 64
#define S_ 1024
#define T_ 1022
#define E_ 256
#define F_ 256
#define H_ 256
#define G_ 1024
#define CS 8          // cluster size (CTAs per cluster)
#define NCLUS 16      // clusters
#define BPC 4         // batches per cluster

// ---------------- device scratch (allocation-free rule: __device__ globals) ----
__device__ float g_xemb[(size_t)B_ * S_ * E_];      // embedded input
__device__ float g_conv[(size_t)B_ * T_ * F_];      // conv output
__device__ float g_gx[(size_t)B_ * T_ * G_];        // gate pre-acts (input side)
__device__ float g_wT[F_ * 3 * E_];                 // conv_w transposed [F][768]
__device__ float g_part[B_][CS];                    // per-(batch,rank) partial sums

// ---------------- helpers ------------------------------------------------------
__device__ __forceinline__ unsigned long long pk2(float x, float y) {
    unsigned long long r;
    asm("mov.b64 %0, {%1, %2};" : "=l"(r) : "f"(x), "f"(y));
    return r;
}
__device__ __forceinline__ void fma2(unsigned long long& d, unsigned long long a,
                                     unsigned long long b) {
    asm("fma.rn.f32x2 %0, %1, %2, %0;" : "+l"(d) : "l"(a), "l"(b));
}
__device__ __forceinline__ float2 up2(unsigned long long v) {
    float2 r;
    asm("mov.b64 {%0, %1}, %2;" : "=f"(r.x), "=f"(r.y) : "l"(v));
    return r;
}
__device__ __forceinline__ uint32_t smem_u32(const void* p) {
    uint32_t a;
    asm("{ .reg .u64 t; cvta.to.shared.u64 t, %1; cvt.u32.u64 %0, t; }"
        : "=r"(a) : "l"(p));
    return a;
}
__device__ __forceinline__ uint32_t cl_rank() {
    uint32_t r; asm("mov.u32 %0, %%cluster_ctarank;" : "=r"(r)); return r;
}
__device__ __forceinline__ uint32_t cl_map(uint32_t laddr, uint32_t rank) {
    uint32_t r;
    asm("mapa.shared::cluster.u32 %0, %1, %2;" : "=r"(r) : "r"(laddr), "r"(rank));
    return r;
}
__device__ __forceinline__ void st_cluster_f32(uint32_t addr, float v) {
    asm volatile("st.shared::cluster.f32 [%0], %1;" :: "r"(addr), "f"(v) : "memory");
}
__device__ __forceinline__ void cl_arrive() {
    asm volatile("barrier.cluster.arrive.aligned;" ::: "memory");
}
__device__ __forceinline__ void cl_wait() {
    asm volatile("barrier.cluster.wait.aligned;" ::: "memory");
}
// tanh via fast exp: tanh(x) = 1 - 2/(e^{2x}+1); saturates correctly at +/-inf.
__device__ __forceinline__ float fast_tanh(float x) {
    return 1.f - __fdividef(2.f, __expf(2.f * x) + 1.f);
}
__device__ __forceinline__ float fast_sig(float x) {
    return __fdividef(1.f, 1.f + __expf(-x));
}

// ---------------- embedding gather -------------------------------------------
__global__ void k_embed(const int* __restrict__ ipts, const float* __restrict__ emb) {
    int row = blockIdx.x;                 // 0 .. B*S-1
    int idx = ipts[row];
    const float4* src = (const float4*)(emb + (size_t)idx * E_);
    float4* dst = (float4*)(g_xemb + (size_t)row * E_);
    dst[threadIdx.x] = src[threadIdx.x];  // 64 threads x float4 = 256 floats
}

// ---------------- conv_w transpose: [768][256] -> [256][768] ------------------
__global__ void k_wt(const float* __restrict__ conv_w) {
    int i = blockIdx.x * blockDim.x + threadIdx.x;
    if (i < 3 * E_ * F_) {
        int we = i / F_, f = i % F_;
        g_wT[f * (3 * E_) + we] = conv_w[i];
    }
}

// ---------------- NT GEMM (R2-proven) + seq-length block skip ------------------
template <int MODE>
__global__ void __launch_bounds__(256)
k_gemm(const float* __restrict__ A, const float* __restrict__ Bm,
       float* __restrict__ C, int M, int N, int K,
       const float* __restrict__ b0, const float* __restrict__ b1,
       const int* __restrict__ slen) {
    const int bm = blockIdx.y * 128;
    {
        int bfirst = bm / T_;
        int tfirst = bm - bfirst * T_;
        int blast = (bm + 127) / T_;
        if (blast == bfirst && tfirst >= slen[bfirst]) return;
    }

    __shared__ float As[16][136];
    __shared__ float Bs[16][136];
    const int tid = threadIdx.x;
    const int bn = blockIdx.x * 128;

    const int lr0 = (tid >> 2), lr1 = lr0 + 64;
    const int k4 = (tid & 3) * 4;

    const float* arow0;
    const float* arow1;
    if (MODE == 0) {
        arow0 = A + (size_t)(bm + lr0) * K;
        arow1 = A + (size_t)(bm + lr1) * K;
    } else {
        unsigned r0 = bm + lr0, r1 = bm + lr1;
        arow0 = A + (size_t)(r0 / T_) * (S_ * E_) + (size_t)(r0 % T_) * E_;
        arow1 = A + (size_t)(r1 / T_) * (S_ * E_) + (size_t)(r1 % T_) * E_;
    }
    const float* brow0 = Bm + (size_t)(bn + lr0) * K;
    const float* brow1 = Bm + (size_t)(bn + lr1) * K;

    const int ty = tid >> 4;
    const int tx = tid & 15;

    float acc[8][8];
#pragma unroll
    for (int i = 0; i < 8; i++)
#pragma unroll
        for (int j = 0; j < 8; j++) acc[i][j] = 0.f;

    for (int k0 = 0; k0 < K; k0 += 16) {
        float4 a0 = *(const float4*)(arow0 + k0 + k4);
        float4 a1 = *(const float4*)(arow1 + k0 + k4);
        float4 c0 = *(const float4*)(brow0 + k0 + k4);
        float4 c1 = *(const float4*)(brow1 + k0 + k4);
        __syncthreads();
        As[k4 + 0][lr0] = a0.x; As[k4 + 1][lr0] = a0.y; As[k4 + 2][lr0] = a0.z; As[k4 + 3][lr0] = a0.w;
        As[k4 + 0][lr1] = a1.x; As[k4 + 1][lr1] = a1.y; As[k4 + 2][lr1] = a1.z; As[k4 + 3][lr1] = a1.w;
        Bs[k4 + 0][lr0] = c0.x; Bs[k4 + 1][lr0] = c0.y; Bs[k4 + 2][lr0] = c0.z; Bs[k4 + 3][lr0] = c0.w;
        Bs[k4 + 0][lr1] = c1.x; Bs[k4 + 1][lr1] = c1.y; Bs[k4 + 2][lr1] = c1.z; Bs[k4 + 3][lr1] = c1.w;
        __syncthreads();
#pragma unroll
        for (int kk = 0; kk < 16; kk++) {
            float4 av0 = *(const float4*)&As[kk][ty * 8];
            float4 av1 = *(const float4*)&As[kk][ty * 8 + 4];
            float4 bv0 = *(const float4*)&Bs[kk][tx * 8];
            float4 bv1 = *(const float4*)&Bs[kk][tx * 8 + 4];
            float a[8] = {av0.x, av0.y, av0.z, av0.w, av1.x, av1.y, av1.z, av1.w};
            float b[8] = {bv0.x, bv0.y, bv0.z, bv0.w, bv1.x, bv1.y, bv1.z, bv1.w};
#pragma unroll
            for (int i = 0; i < 8; i++)
#pragma unroll
                for (int j = 0; j < 8; j++) acc[i][j] += a[i] * b[j];
        }
    }

    float bb[8];
#pragma unroll
    for (int j = 0; j < 8; j++) {
        int n = bn + tx * 8 + j;
        float v = b0 ? b0[n] : 0.f;
        if (b1) v += b1[n];
        bb[j] = v;
    }
#pragma unroll
    for (int i = 0; i < 8; i++) {
        float* crow = C + (size_t)(bm + ty * 8 + i) * N + bn + tx * 8;
        float4 v0, v1;
        v0.x = acc[i][0] + bb[0]; v0.y = acc[i][1] + bb[1];
        v0.z = acc[i][2] + bb[2]; v0.w = acc[i][3] + bb[3];
        v1.x = acc[i][4] + bb[4]; v1.y = acc[i][5] + bb[5];
        v1.z = acc[i][6] + bb[6]; v1.w = acc[i][7] + bb[7];
        *(float4*)(crow) = v0;
        *(float4*)(crow + 4) = v1;
    }
}

// ---------------- cluster LSTM, register-resident W_hh (R10-proven skeleton) ---
// Only delta vs R10: fast_sig/fast_tanh in the activation phase (pure ALU).
__global__ void __launch_bounds__(256) __cluster_dims__(CS, 1, 1)
k_lstm(const float* __restrict__ w_hh, const float* __restrict__ h0,
       const float* __restrict__ c0, const int* __restrict__ slen,
       const float* __restrict__ lin_w) {
    __shared__ float Hf[2 * 128 * BPC * 2];   // [buf][kp][b][2]    8 KB
    __shared__ float Gs[4 * BPC * 132];       // [kq][b][132]       8.4 KB

    const int tid = threadIdx.x;
    const uint32_t rank = cl_rank();
    const int b0g = (blockIdx.x >> 3) * BPC;
    const int r0 = tid & 63;            // owns rows r0 (gates 0/1) and r0+64 (gates 2/3)
    const int kq = tid >> 6;            // k-quarter 0..3 (64 k values = 32 pairs)

    // ---- W_hh rows into REGISTERS (loaded once, reused all steps) ------------
    unsigned long long W0[32], W1[32];
    {
        const int g0 = r0 >> 5, j0 = r0 & 31;              // row r0
        const int g1 = (r0 + 64) >> 5, j1 = r0 & 31;       // row r0+64
        const float2* s0 = (const float2*)(w_hh + (size_t)(g0 * H_ + rank * 32 + j0) * H_) + kq * 32;
        const float2* s1 = (const float2*)(w_hh + (size_t)(g1 * H_ + rank * 32 + j1) * H_) + kq * 32;
#pragma unroll
        for (int i = 0; i < 32; i++) {
            float2 a = s0[i]; W0[i] = pk2(a.x, a.y);
            float2 b = s1[i]; W1[i] = pk2(b.x, b.y);
        }
    }
    // ---- init h buffer 0 from h0 ----------------------------------------------
    if (tid < 128) {
#pragma unroll
        for (int b = 0; b < BPC; b++) {
            float2 v = *(const float2*)(h0 + (size_t)(b0g + b) * H_ + 2 * tid);
            Hf[tid * 8 + b * 2 + 0] = v.x;
            Hf[tid * 8 + b * 2 + 1] = v.y;
        }
    }

    // ---- activation ownership (threads 0..127): (bl, jl) ----------------------
    const int bl = tid >> 5, jl = tid & 31;
    const int bg = b0g + bl;
    const int jglob = rank * 32 + jl;
    float c = 0.f, hsum = 0.f;
    int mylen = 0;
    const float* gxp[4];
    if (tid < 128) {
        c = c0[bg * H_ + jglob];
        mylen = slen[bg];
#pragma unroll
        for (int g = 0; g < 4; g++)
            gxp[g] = g_gx + (size_t)bg * T_ * G_ + (size_t)g * H_ + jglob;
    }
    int tmax = 0;
#pragma unroll
    for (int b = 0; b < BPC; b++) tmax = max(tmax, slen[b0g + b]);

    // peer SMEM addresses of the h buffer (for DSMEM broadcast of new h)
    const uint32_t h_local = smem_u32(Hf);
    uint32_t peer[CS];
#pragma unroll
    for (int r = 0; r < CS; r++) peer[r] = cl_map(h_local, r);

    __syncthreads();
    cl_arrive();
    // prefetch step 0's input-side gate pre-acts while the barrier settles
    float gx0 = 0.f, gx1 = 0.f, gx2 = 0.f, gx3 = 0.f;
    if (tid < 128) {
        gx0 = __ldg(gxp[0]); gx1 = __ldg(gxp[1]);
        gx2 = __ldg(gxp[2]); gx3 = __ldg(gxp[3]);
    }
    cl_wait();   // all CTAs initialized before any remote traffic

    for (int t = 0; t < tmax; t++) {
        const int cur = t & 1, nxt = cur ^ 1;

        // mini-GEMM: all W from registers, h via broadcast LDS
        unsigned long long a00 = 0ull, a01 = 0ull, a02 = 0ull, a03 = 0ull;
        unsigned long long a10 = 0ull, a11 = 0ull, a12 = 0ull, a13 = 0ull;
        const float* hb = Hf + cur * (128 * BPC * 2) + kq * 32 * 8;
#pragma unroll
        for (int i = 0; i < 32; i++) {
            const ulonglong2* hp = (const ulonglong2*)(hb + i * 8);
            ulonglong2 u01 = hp[0];
            ulonglong2 u23 = hp[1];
            fma2(a00, u01.x, W0[i]); fma2(a01, u01.y, W0[i]);
            fma2(a02, u23.x, W0[i]); fma2(a03, u23.y, W0[i]);
            fma2(a10, u01.x, W1[i]); fma2(a11, u01.y, W1[i]);
            fma2(a12, u23.x, W1[i]); fma2(a13, u23.y, W1[i]);
        }
        {
            float* gs = Gs + kq * (BPC * 132);
            float2 p;
            p = up2(a00); gs[0 * 132 + r0] = p.x + p.y;
            p = up2(a01); gs[1 * 132 + r0] = p.x + p.y;
            p = up2(a02); gs[2 * 132 + r0] = p.x + p.y;
            p = up2(a03); gs[3 * 132 + r0] = p.x + p.y;
            p = up2(a10); gs[0 * 132 + r0 + 64] = p.x + p.y;
            p = up2(a11); gs[1 * 132 + r0 + 64] = p.x + p.y;
            p = up2(a12); gs[2 * 132 + r0 + 64] = p.x + p.y;
            p = up2(a13); gs[3 * 132 + r0 + 64] = p.x + p.y;
        }
        __syncthreads();

        // activations + state update; broadcast new h to all cluster CTAs
        if (tid < 128) {
            float gi = gx0, gf = gx1, gg = gx2, go = gx3;
#pragma unroll
            for (int q = 0; q < 4; q++) {
                const float* gsq = Gs + q * (BPC * 132) + bl * 132 + jl;
                gi += gsq[0];
                gf += gsq[32];
                gg += gsq[64];
                go += gsq[96];
            }
            float si = fast_sig(gi);
            float sf = fast_sig(gf);
            float so = fast_sig(go);
            c = sf * c + si * fast_tanh(gg);
            float h = so * fast_tanh(c);
            if (t < mylen) hsum += h;
            const uint32_t off =
                (uint32_t)(nxt * (128 * BPC * 2) + (jglob >> 1) * 8 + bl * 2 + (jglob & 1)) * 4u;
#pragma unroll
            for (int r = 0; r < CS; r++) st_cluster_f32(peer[r] + off, h);
        }
        cl_arrive();
        // overlap next step's gx prefetch with the cluster-barrier wait
        if (tid < 128 && (t + 1 < tmax)) {
            const size_t toff = (size_t)(t + 1) * G_;
            gx0 = __ldg(gxp[0] + toff);
            gx1 = __ldg(gxp[1] + toff);
            gx2 = __ldg(gxp[2] + toff);
            gx3 = __ldg(gxp[3] + toff);
        }
        cl_wait();
    }
    cl_arrive(); cl_wait();   // drain in-flight remote stores before exit

    // ---- masked-sum . lin_w: warp = one batch, lanes = 32 j's -----------------
    if (tid < 128) {
        float v = hsum * lin_w[jglob];
        v += __shfl_xor_sync(0xffffffffu, v, 16);
        v += __shfl_xor_sync(0xffffffffu, v, 8);
        v += __shfl_xor_sync(0xffffffffu, v, 4);
        v += __shfl_xor_sync(0xffffffffu, v, 2);
        v += __shfl_xor_sync(0xffffffffu, v, 1);
        if (jl == 0) g_part[bg][rank] = v;
    }
}

// ---------------- finisher -----------------------------------------------------
__global__ void k_final(const int* __restrict__ slen, const float* __restrict__ lin_b,
                        float* __restrict__ out) {
    int b = threadIdx.x;  // 64
    float s = 0.f;
#pragma unroll
    for (int r = 0; r < CS; r++) s += g_part[b][r];
    float v = s / (float)slen[b] + lin_b[0];
    out[b] = 1.f / (1.f + expf(-v));
}

// ---------------- launch -------------------------------------------------------
extern "C" void kernel_launch(void* const* d_in, const int* in_sizes, int n_in,
                              void* d_out, int out_size) {
    const int*   ipts  = (const int*)d_in[0];
    const int*   slen  = (const int*)d_in[1];
    const float* h0    = (const float*)d_in[2];
    const float* c0    = (const float*)d_in[3];
    const float* emb   = (const float*)d_in[4];
    const float* convw = (const float*)d_in[5];
    const float* convb = (const float*)d_in[6];
    const float* w_ih  = (const float*)d_in[7];
    const float* w_hh  = (const float*)d_in[8];
    const float* b_ih  = (const float*)d_in[9];
    const float* b_hh  = (const float*)d_in[10];
    const float* lin_w = (const float*)d_in[11];
    const float* lin_b = (const float*)d_in[12];
    float* out = (float*)d_out;

    float *p_xemb, *p_conv, *p_gx, *p_wT;
    cudaGetSymbolAddress((void**)&p_xemb, g_xemb);
    cudaGetSymbolAddress((void**)&p_conv, g_conv);
    cudaGetSymbolAddress((void**)&p_gx, g_gx);
    cudaGetSymbolAddress((void**)&p_wT, g_wT);

    // 1) embedding gather
    k_embed<<<B_ * S_, 64>>>(ipts, emb);
    // 2) transpose conv weights to [F][768]
    k_wt<<<(3 * E_ * F_ + 255) / 256, 256>>>(convw);
    // 3) conv as NT GEMM over contiguous 768-float windows (skips t >= len[b])
    {
        dim3 g(F_ / 128, (B_ * T_) / 128);  // (2, 511)
        k_gemm<1><<<g, 256>>>(p_xemb, p_wT, p_conv, B_ * T_, F_, 3 * E_, convb, nullptr, slen);
    }
    // 4) input projection: gates_x = conv_out @ w_ih^T + (b_ih+b_hh) (skips too)
    {
        dim3 g(G_ / 128, (B_ * T_) / 128);  // (8, 511)
        k_gemm<0><<<g, 256>>>(p_conv, w_ih, p_gx, B_ * T_, G_, F_, b_ih, b_hh, slen);
    }
    // 5) cluster LSTM recurrence (W in registers, barrier.cluster sync)
    k_lstm<<<NCLUS * CS, 256>>>(w_hh, h0, c0, slen, lin_w);
    // 6) final: masked mean . linear . sigmoid
    k_final<<<1, 64>>>(slen, lin_b, out);
}

// round 14
// speedup vs baseline: 1.0167x; 1.0167x over previous
#include <cuda_runtime.h>
#include <math.h>
#include <stdint.h>

#define B_ 64
#define S_ 1024
#define T_ 1022
#define E_ 256
#define F_ 256
#define H_ 256
#define G_ 1024
#define CS 8          // cluster size (CTAs per cluster)
#define NCLUS 16      // clusters
#define BPC 4         // batches per cluster

// ---------------- device scratch (allocation-free rule: __device__ globals) ----
__device__ float g_xemb[(size_t)B_ * S_ * E_];      // embedded input
__device__ float g_conv[(size_t)B_ * T_ * F_];      // conv output
__device__ float g_gx[(size_t)B_ * T_ * G_];        // gate pre-acts (input side)
__device__ float g_wT[F_ * 3 * E_];                 // conv_w transposed [F][768]
__device__ float g_part[B_][CS];                    // per-(batch,rank) partial sums

// ---------------- helpers ------------------------------------------------------
__device__ __forceinline__ unsigned long long pk2(float x, float y) {
    unsigned long long r;
    asm("mov.b64 %0, {%1, %2};" : "=l"(r) : "f"(x), "f"(y));
    return r;
}
__device__ __forceinline__ void fma2(unsigned long long& d, unsigned long long a,
                                     unsigned long long b) {
    asm("fma.rn.f32x2 %0, %1, %2, %0;" : "+l"(d) : "l"(a), "l"(b));
}
__device__ __forceinline__ float2 up2(unsigned long long v) {
    float2 r;
    asm("mov.b64 {%0, %1}, %2;" : "=f"(r.x), "=f"(r.y) : "l"(v));
    return r;
}
__device__ __forceinline__ uint32_t smem_u32(const void* p) {
    uint32_t a;
    asm("{ .reg .u64 t; cvta.to.shared.u64 t, %1; cvt.u32.u64 %0, t; }"
        : "=r"(a) : "l"(p));
    return a;
}
__device__ __forceinline__ uint32_t cl_rank() {
    uint32_t r; asm("mov.u32 %0, %%cluster_ctarank;" : "=r"(r)); return r;
}
__device__ __forceinline__ uint32_t cl_map(uint32_t laddr, uint32_t rank) {
    uint32_t r;
    asm("mapa.shared::cluster.u32 %0, %1, %2;" : "=r"(r) : "r"(laddr), "r"(rank));
    return r;
}
__device__ __forceinline__ void st_cluster_f32x2(uint32_t addr, float lo, float hi) {
    asm volatile("st.shared::cluster.v2.f32 [%0], {%1, %2};"
                 :: "r"(addr), "f"(lo), "f"(hi) : "memory");
}
__device__ __forceinline__ void cl_arrive() {
    asm volatile("barrier.cluster.arrive.aligned;" ::: "memory");
}
__device__ __forceinline__ void cl_wait() {
    asm volatile("barrier.cluster.wait.aligned;" ::: "memory");
}

// ---------------- embedding gather -------------------------------------------
__global__ void k_embed(const int* __restrict__ ipts, const float* __restrict__ emb) {
    int row = blockIdx.x;                 // 0 .. B*S-1
    int idx = ipts[row];
    const float4* src = (const float4*)(emb + (size_t)idx * E_);
    float4* dst = (float4*)(g_xemb + (size_t)row * E_);
    dst[threadIdx.x] = src[threadIdx.x];  // 64 threads x float4 = 256 floats
}

// ---------------- conv_w transpose: [768][256] -> [256][768] ------------------
__global__ void k_wt(const float* __restrict__ conv_w) {
    int i = blockIdx.x * blockDim.x + threadIdx.x;
    if (i < 3 * E_ * F_) {
        int we = i / F_, f = i % F_;
        g_wT[f * (3 * E_) + we] = conv_w[i];
    }
}

// ---------------- NT GEMM (R2-proven) + seq-length block skip ------------------
template <int MODE>
__global__ void __launch_bounds__(256)
k_gemm(const float* __restrict__ A, const float* __restrict__ Bm,
       float* __restrict__ C, int M, int N, int K,
       const float* __restrict__ b0, const float* __restrict__ b1,
       const int* __restrict__ slen) {
    const int bm = blockIdx.y * 128;
    {
        int bfirst = bm / T_;
        int tfirst = bm - bfirst * T_;
        int blast = (bm + 127) / T_;
        if (blast == bfirst && tfirst >= slen[bfirst]) return;
    }

    __shared__ float As[16][136];
    __shared__ float Bs[16][136];
    const int tid = threadIdx.x;
    const int bn = blockIdx.x * 128;

    const int lr0 = (tid >> 2), lr1 = lr0 + 64;
    const int k4 = (tid & 3) * 4;

    const float* arow0;
    const float* arow1;
    if (MODE == 0) {
        arow0 = A + (size_t)(bm + lr0) * K;
        arow1 = A + (size_t)(bm + lr1) * K;
    } else {
        unsigned r0 = bm + lr0, r1 = bm + lr1;
        arow0 = A + (size_t)(r0 / T_) * (S_ * E_) + (size_t)(r0 % T_) * E_;
        arow1 = A + (size_t)(r1 / T_) * (S_ * E_) + (size_t)(r1 % T_) * E_;
    }
    const float* brow0 = Bm + (size_t)(bn + lr0) * K;
    const float* brow1 = Bm + (size_t)(bn + lr1) * K;

    const int ty = tid >> 4;
    const int tx = tid & 15;

    float acc[8][8];
#pragma unroll
    for (int i = 0; i < 8; i++)
#pragma unroll
        for (int j = 0; j < 8; j++) acc[i][j] = 0.f;

    for (int k0 = 0; k0 < K; k0 += 16) {
        float4 a0 = *(const float4*)(arow0 + k0 + k4);
        float4 a1 = *(const float4*)(arow1 + k0 + k4);
        float4 c0 = *(const float4*)(brow0 + k0 + k4);
        float4 c1 = *(const float4*)(brow1 + k0 + k4);
        __syncthreads();
        As[k4 + 0][lr0] = a0.x; As[k4 + 1][lr0] = a0.y; As[k4 + 2][lr0] = a0.z; As[k4 + 3][lr0] = a0.w;
        As[k4 + 0][lr1] = a1.x; As[k4 + 1][lr1] = a1.y; As[k4 + 2][lr1] = a1.z; As[k4 + 3][lr1] = a1.w;
        Bs[k4 + 0][lr0] = c0.x; Bs[k4 + 1][lr0] = c0.y; Bs[k4 + 2][lr0] = c0.z; Bs[k4 + 3][lr0] = c0.w;
        Bs[k4 + 0][lr1] = c1.x; Bs[k4 + 1][lr1] = c1.y; Bs[k4 + 2][lr1] = c1.z; Bs[k4 + 3][lr1] = c1.w;
        __syncthreads();
#pragma unroll
        for (int kk = 0; kk < 16; kk++) {
            float4 av0 = *(const float4*)&As[kk][ty * 8];
            float4 av1 = *(const float4*)&As[kk][ty * 8 + 4];
            float4 bv0 = *(const float4*)&Bs[kk][tx * 8];
            float4 bv1 = *(const float4*)&Bs[kk][tx * 8 + 4];
            float a[8] = {av0.x, av0.y, av0.z, av0.w, av1.x, av1.y, av1.z, av1.w};
            float b[8] = {bv0.x, bv0.y, bv0.z, bv0.w, bv1.x, bv1.y, bv1.z, bv1.w};
#pragma unroll
            for (int i = 0; i < 8; i++)
#pragma unroll
                for (int j = 0; j < 8; j++) acc[i][j] += a[i] * b[j];
        }
    }

    float bb[8];
#pragma unroll
    for (int j = 0; j < 8; j++) {
        int n = bn + tx * 8 + j;
        float v = b0 ? b0[n] : 0.f;
        if (b1) v += b1[n];
        bb[j] = v;
    }
#pragma unroll
    for (int i = 0; i < 8; i++) {
        float* crow = C + (size_t)(bm + ty * 8 + i) * N + bn + tx * 8;
        float4 v0, v1;
        v0.x = acc[i][0] + bb[0]; v0.y = acc[i][1] + bb[1];
        v0.z = acc[i][2] + bb[2]; v0.w = acc[i][3] + bb[3];
        v1.x = acc[i][4] + bb[4]; v1.y = acc[i][5] + bb[5];
        v1.z = acc[i][6] + bb[6]; v1.w = acc[i][7] + bb[7];
        *(float4*)(crow) = v0;
        *(float4*)(crow + 4) = v1;
    }
}

// ---------------- cluster LSTM, register-resident W_hh (R10 skeleton) ----------
// Only delta vs the 3193us R10 kernel: paired lanes issue ONE v2.f32 remote
// store per peer (halves outstanding DSMEM stores the barrier must drain).
// Activation arithmetic is byte-identical to R10 (libm tanhf) so rel_err must
// reproduce exactly.
__global__ void __launch_bounds__(256) __cluster_dims__(CS, 1, 1)
k_lstm(const float* __restrict__ w_hh, const float* __restrict__ h0,
       const float* __restrict__ c0, const int* __restrict__ slen,
       const float* __restrict__ lin_w) {
    __shared__ float Hf[2 * 128 * BPC * 2];   // [buf][kp][b][2]    8 KB
    __shared__ float Gs[4 * BPC * 132];       // [kq][b][132]       8.4 KB

    const int tid = threadIdx.x;
    const uint32_t rank = cl_rank();
    const int b0g = (blockIdx.x >> 3) * BPC;
    const int r0 = tid & 63;            // owns rows r0 (gates 0/1) and r0+64 (gates 2/3)
    const int kq = tid >> 6;            // k-quarter 0..3 (64 k values = 32 pairs)

    // ---- W_hh rows into REGISTERS (loaded once, reused all steps) ------------
    unsigned long long W0[32], W1[32];
    {
        const int g0 = r0 >> 5, j0 = r0 & 31;              // row r0
        const int g1 = (r0 + 64) >> 5, j1 = r0 & 31;       // row r0+64
        const float2* s0 = (const float2*)(w_hh + (size_t)(g0 * H_ + rank * 32 + j0) * H_) + kq * 32;
        const float2* s1 = (const float2*)(w_hh + (size_t)(g1 * H_ + rank * 32 + j1) * H_) + kq * 32;
#pragma unroll
        for (int i = 0; i < 32; i++) {
            float2 a = s0[i]; W0[i] = pk2(a.x, a.y);
            float2 b = s1[i]; W1[i] = pk2(b.x, b.y);
        }
    }
    // ---- init h buffer 0 from h0 ----------------------------------------------
    if (tid < 128) {
#pragma unroll
        for (int b = 0; b < BPC; b++) {
            float2 v = *(const float2*)(h0 + (size_t)(b0g + b) * H_ + 2 * tid);
            Hf[tid * 8 + b * 2 + 0] = v.x;
            Hf[tid * 8 + b * 2 + 1] = v.y;
        }
    }

    // ---- activation ownership (threads 0..127): (bl, jl) ----------------------
    const int bl = tid >> 5, jl = tid & 31;
    const int bg = b0g + bl;
    const int jglob = rank * 32 + jl;
    float c = 0.f, hsum = 0.f;
    int mylen = 0;
    const float* gxp[4];
    if (tid < 128) {
        c = c0[bg * H_ + jglob];
        mylen = slen[bg];
#pragma unroll
        for (int g = 0; g < 4; g++)
            gxp[g] = g_gx + (size_t)bg * T_ * G_ + (size_t)g * H_ + jglob;
    }
    int tmax = 0;
#pragma unroll
    for (int b = 0; b < BPC; b++) tmax = max(tmax, slen[b0g + b]);

    // peer SMEM addresses of the h buffer (for paired DSMEM broadcast of new h)
    const uint32_t h_local = smem_u32(Hf);
    uint32_t peer[CS];
#pragma unroll
    for (int r = 0; r < CS; r++) peer[r] = cl_map(h_local, r);

    __syncthreads();
    cl_arrive();
    // prefetch step 0's input-side gate pre-acts while the barrier settles
    float gx0 = 0.f, gx1 = 0.f, gx2 = 0.f, gx3 = 0.f;
    if (tid < 128) {
        gx0 = __ldg(gxp[0]); gx1 = __ldg(gxp[1]);
        gx2 = __ldg(gxp[2]); gx3 = __ldg(gxp[3]);
    }
    cl_wait();   // all CTAs initialized before any remote traffic

    for (int t = 0; t < tmax; t++) {
        const int cur = t & 1, nxt = cur ^ 1;

        // mini-GEMM: all W from registers, h via broadcast LDS
        unsigned long long a00 = 0ull, a01 = 0ull, a02 = 0ull, a03 = 0ull;
        unsigned long long a10 = 0ull, a11 = 0ull, a12 = 0ull, a13 = 0ull;
        const float* hb = Hf + cur * (128 * BPC * 2) + kq * 32 * 8;
#pragma unroll
        for (int i = 0; i < 32; i++) {
            const ulonglong2* hp = (const ulonglong2*)(hb + i * 8);
            ulonglong2 u01 = hp[0];
            ulonglong2 u23 = hp[1];
            fma2(a00, u01.x, W0[i]); fma2(a01, u01.y, W0[i]);
            fma2(a02, u23.x, W0[i]); fma2(a03, u23.y, W0[i]);
            fma2(a10, u01.x, W1[i]); fma2(a11, u01.y, W1[i]);
            fma2(a12, u23.x, W1[i]); fma2(a13, u23.y, W1[i]);
        }
        {
            float* gs = Gs + kq * (BPC * 132);
            float2 p;
            p = up2(a00); gs[0 * 132 + r0] = p.x + p.y;
            p = up2(a01); gs[1 * 132 + r0] = p.x + p.y;
            p = up2(a02); gs[2 * 132 + r0] = p.x + p.y;
            p = up2(a03); gs[3 * 132 + r0] = p.x + p.y;
            p = up2(a10); gs[0 * 132 + r0 + 64] = p.x + p.y;
            p = up2(a11); gs[1 * 132 + r0 + 64] = p.x + p.y;
            p = up2(a12); gs[2 * 132 + r0 + 64] = p.x + p.y;
            p = up2(a13); gs[3 * 132 + r0 + 64] = p.x + p.y;
        }
        __syncthreads();

        // activations + state update; paired 64-bit broadcast to all cluster CTAs
        if (tid < 128) {
            float gi = gx0, gf = gx1, gg = gx2, go = gx3;
#pragma unroll
            for (int q = 0; q < 4; q++) {
                const float* gsq = Gs + q * (BPC * 132) + bl * 132 + jl;
                gi += gsq[0];
                gf += gsq[32];
                gg += gsq[64];
                go += gsq[96];
            }
            float si = 1.f / (1.f + __expf(-gi));
            float sf = 1.f / (1.f + __expf(-gf));
            float so = 1.f / (1.f + __expf(-go));
            c = sf * c + si * tanhf(gg);
            float h = so * tanhf(c);
            if (t < mylen) hsum += h;
            // lanes (jl even, jl odd) pair up -> one v2.f32 store per peer
            float hpart = __shfl_xor_sync(0xffffffffu, h, 1);
            if ((jl & 1) == 0) {
                // jglob even here; pair occupies floats (kp*8 + bl*2) + {0,1}
                const uint32_t off =
                    (uint32_t)(nxt * (128 * BPC * 2) + (jglob >> 1) * 8 + bl * 2) * 4u;
#pragma unroll
                for (int r = 0; r < CS; r++)
                    st_cluster_f32x2(peer[r] + off, h, hpart);
            }
        }
        cl_arrive();
        // overlap next step's gx prefetch with the cluster-barrier wait
        if (tid < 128 && (t + 1 < tmax)) {
            const size_t toff = (size_t)(t + 1) * G_;
            gx0 = __ldg(gxp[0] + toff);
            gx1 = __ldg(gxp[1] + toff);
            gx2 = __ldg(gxp[2] + toff);
            gx3 = __ldg(gxp[3] + toff);
        }
        cl_wait();
    }
    cl_arrive(); cl_wait();   // drain in-flight remote stores before exit

    // ---- masked-sum . lin_w: warp = one batch, lanes = 32 j's -----------------
    if (tid < 128) {
        float v = hsum * lin_w[jglob];
        v += __shfl_xor_sync(0xffffffffu, v, 16);
        v += __shfl_xor_sync(0xffffffffu, v, 8);
        v += __shfl_xor_sync(0xffffffffu, v, 4);
        v += __shfl_xor_sync(0xffffffffu, v, 2);
        v += __shfl_xor_sync(0xffffffffu, v, 1);
        if (jl == 0) g_part[bg][rank] = v;
    }
}

// ---------------- finisher -----------------------------------------------------
__global__ void k_final(const int* __restrict__ slen, const float* __restrict__ lin_b,
                        float* __restrict__ out) {
    int b = threadIdx.x;  // 64
    float s = 0.f;
#pragma unroll
    for (int r = 0; r < CS; r++) s += g_part[b][r];
    float v = s / (float)slen[b] + lin_b[0];
    out[b] = 1.f / (1.f + expf(-v));
}

// ---------------- launch -------------------------------------------------------
extern "C" void kernel_launch(void* const* d_in, const int* in_sizes, int n_in,
                              void* d_out, int out_size) {
    const int*   ipts  = (const int*)d_in[0];
    const int*   slen  = (const int*)d_in[1];
    const float* h0    = (const float*)d_in[2];
    const float* c0    = (const float*)d_in[3];
    const float* emb   = (const float*)d_in[4];
    const float* convw = (const float*)d_in[5];
    const float* convb = (const float*)d_in[6];
    const float* w_ih  = (const float*)d_in[7];
    const float* w_hh  = (const float*)d_in[8];
    const float* b_ih  = (const float*)d_in[9];
    const float* b_hh  = (const float*)d_in[10];
    const float* lin_w = (const float*)d_in[11];
    const float* lin_b = (const float*)d_in[12];
    float* out = (float*)d_out;

    float *p_xemb, *p_conv, *p_gx, *p_wT;
    cudaGetSymbolAddress((void**)&p_xemb, g_xemb);
    cudaGetSymbolAddress((void**)&p_conv, g_conv);
    cudaGetSymbolAddress((void**)&p_gx, g_gx);
    cudaGetSymbolAddress((void**)&p_wT, g_wT);

    // 1) embedding gather
    k_embed<<<B_ * S_, 64>>>(ipts, emb);
    // 2) transpose conv weights to [F][768]
    k_wt<<<(3 * E_ * F_ + 255) / 256, 256>>>(convw);
    // 3) conv as NT GEMM over contiguous 768-float windows (skips t >= len[b])
    {
        dim3 g(F_ / 128, (B_ * T_) / 128);  // (2, 511)
        k_gemm<1><<<g, 256>>>(p_xemb, p_wT, p_conv, B_ * T_, F_, 3 * E_, convb, nullptr, slen);
    }
    // 4) input projection: gates_x = conv_out @ w_ih^T + (b_ih+b_hh) (skips too)
    {
        dim3 g(G_ / 128, (B_ * T_) / 128);  // (8, 511)
        k_gemm<0><<<g, 256>>>(p_conv, w_ih, p_gx, B_ * T_, G_, F_, b_ih, b_hh, slen);
    }
    // 5) cluster LSTM recurrence (W in registers, barrier.cluster, paired stores)
    k_lstm<<<NCLUS * CS, 256>>>(w_hh, h0, c0, slen, lin_w);
    // 6) final: masked mean . linear . sigmoid
    k_final<<<1, 64>>>(slen, lin_b, out);
}

// round 15
// speedup vs baseline: 1.0310x; 1.0140x over previous
#include <cuda_runtime.h>
#include <math.h>
#include <stdint.h>

#define B_ 64
#define S_ 1024
#define T_ 1022
#define E_ 256
#define F_ 256
#define H_ 256
#define G_ 1024
#define CS 8          // cluster size (CTAs per cluster)
#define NCLUS 16      // clusters
#define BPC 4         // batches per cluster

// ---------------- device scratch (allocation-free rule: __device__ globals) ----
__device__ float g_xemb[(size_t)B_ * S_ * E_];      // embedded input
__device__ float g_conv[(size_t)B_ * T_ * F_];      // conv output
__device__ float g_gx[(size_t)B_ * T_ * G_];        // gate pre-acts (input side)
__device__ float g_wT[F_ * 3 * E_];                 // conv_w transposed [F][768]
__device__ float g_part[B_][CS];                    // per-(batch,rank) partial sums

// ---------------- helpers ------------------------------------------------------
__device__ __forceinline__ unsigned long long pk2(float x, float y) {
    unsigned long long r;
    asm("mov.b64 %0, {%1, %2};" : "=l"(r) : "f"(x), "f"(y));
    return r;
}
__device__ __forceinline__ void fma2(unsigned long long& d, unsigned long long a,
                                     unsigned long long b) {
    asm("fma.rn.f32x2 %0, %1, %2, %0;" : "+l"(d) : "l"(a), "l"(b));
}
__device__ __forceinline__ float2 up2(unsigned long long v) {
    float2 r;
    asm("mov.b64 {%0, %1}, %2;" : "=f"(r.x), "=f"(r.y) : "l"(v));
    return r;
}
__device__ __forceinline__ uint32_t smem_u32(const void* p) {
    uint32_t a;
    asm("{ .reg .u64 t; cvta.to.shared.u64 t, %1; cvt.u32.u64 %0, t; }"
        : "=r"(a) : "l"(p));
    return a;
}
__device__ __forceinline__ uint32_t cl_rank() {
    uint32_t r; asm("mov.u32 %0, %%cluster_ctarank;" : "=r"(r)); return r;
}
__device__ __forceinline__ uint32_t cl_map(uint32_t laddr, uint32_t rank) {
    uint32_t r;
    asm("mapa.shared::cluster.u32 %0, %1, %2;" : "=r"(r) : "r"(laddr), "r"(rank));
    return r;
}
__device__ __forceinline__ void st_cluster_f32x2(uint32_t addr, float lo, float hi) {
    asm volatile("st.shared::cluster.v2.f32 [%0], {%1, %2};"
                 :: "r"(addr), "f"(lo), "f"(hi) : "memory");
}
__device__ __forceinline__ void cl_arrive() {
    asm volatile("barrier.cluster.arrive.aligned;" ::: "memory");
}
__device__ __forceinline__ void cl_wait() {
    asm volatile("barrier.cluster.wait.aligned;" ::: "memory");
}

// ---------------- embedding gather (bulk blocks + dead-row skip) ---------------
// Row (b,s) is only ever read by conv windows t < len[b] (s <= t+2 < len[b]+2).
// Rows with s >= len[b]+2 feed only dead conv/gx lanes -> skip (same dead-lane
// argument already validated bit-exact by the gemm block-skip).
__global__ void k_embed(const int* __restrict__ ipts, const float* __restrict__ emb,
                        const int* __restrict__ slen) {
    const int base = blockIdx.x * 64;            // 64 rows per block
#pragma unroll
    for (int i = 0; i < 16; i++) {
        int flat = i * 256 + threadIdx.x;        // 0..4095 over 64 rows x 64 f4
        int rl = flat >> 6, c = flat & 63;
        int row = base + rl;
        int b = row >> 10, s = row & 1023;
        if (s < slen[b] + 2) {
            int idx = ipts[row];
            ((float4*)(g_xemb + (size_t)row * E_))[c] =
                ((const float4*)(emb + (size_t)idx * E_))[c];
        }
    }
}

// ---------------- conv_w transpose: [768][256] -> [256][768] ------------------
__global__ void k_wt(const float* __restrict__ conv_w) {
    int i = blockIdx.x * blockDim.x + threadIdx.x;
    if (i < 3 * E_ * F_) {
        int we = i / F_, f = i % F_;
        g_wT[f * (3 * E_) + we] = conv_w[i];
    }
}

// ---------------- NT GEMM: 128x128x16, 2-stage smem, regs capped at 128 --------
// Block skip: rows map to (b=m/T_, t=m%T_); blocks fully past len[b] are dead.
// MODE 0: A row m at A + m*K. MODE 1: conv windows (contiguous 768 floats).
template <int MODE>
__global__ void __launch_bounds__(256, 2)
k_gemm(const float* __restrict__ A, const float* __restrict__ Bm,
       float* __restrict__ C, int M, int N, int K,
       const float* __restrict__ b0, const float* __restrict__ b1,
       const int* __restrict__ slen) {
    const int bm = blockIdx.y * 128;
    {
        int bfirst = bm / T_;
        int tfirst = bm - bfirst * T_;
        int blast = (bm + 127) / T_;
        if (blast == bfirst && tfirst >= slen[bfirst]) return;
    }

    __shared__ float As[2][16][136];
    __shared__ float Bs[2][16][136];
    const int tid = threadIdx.x;
    const int bn = blockIdx.x * 128;

    const int lr0 = (tid >> 2), lr1 = lr0 + 64;
    const int k4 = (tid & 3) * 4;

    const float* arow0;
    const float* arow1;
    if (MODE == 0) {
        arow0 = A + (size_t)(bm + lr0) * K;
        arow1 = A + (size_t)(bm + lr1) * K;
    } else {
        unsigned r0 = bm + lr0, r1 = bm + lr1;
        arow0 = A + (size_t)(r0 / T_) * (S_ * E_) + (size_t)(r0 % T_) * E_;
        arow1 = A + (size_t)(r1 / T_) * (S_ * E_) + (size_t)(r1 % T_) * E_;
    }
    const float* brow0 = Bm + (size_t)(bn + lr0) * K;
    const float* brow1 = Bm + (size_t)(bn + lr1) * K;

    const int ty = tid >> 4;
    const int tx = tid & 15;

    float acc[8][8];
#pragma unroll
    for (int i = 0; i < 8; i++)
#pragma unroll
        for (int j = 0; j < 8; j++) acc[i][j] = 0.f;

    // prologue: fill stage 0
    {
        float4 a0 = *(const float4*)(arow0 + k4);
        float4 a1 = *(const float4*)(arow1 + k4);
        float4 c0 = *(const float4*)(brow0 + k4);
        float4 c1 = *(const float4*)(brow1 + k4);
        As[0][k4 + 0][lr0] = a0.x; As[0][k4 + 1][lr0] = a0.y; As[0][k4 + 2][lr0] = a0.z; As[0][k4 + 3][lr0] = a0.w;
        As[0][k4 + 0][lr1] = a1.x; As[0][k4 + 1][lr1] = a1.y; As[0][k4 + 2][lr1] = a1.z; As[0][k4 + 3][lr1] = a1.w;
        Bs[0][k4 + 0][lr0] = c0.x; Bs[0][k4 + 1][lr0] = c0.y; Bs[0][k4 + 2][lr0] = c0.z; Bs[0][k4 + 3][lr0] = c0.w;
        Bs[0][k4 + 0][lr1] = c1.x; Bs[0][k4 + 1][lr1] = c1.y; Bs[0][k4 + 2][lr1] = c1.z; Bs[0][k4 + 3][lr1] = c1.w;
    }
    __syncthreads();

    int s = 0;
    for (int k0 = 0; k0 < K; k0 += 16) {
        const bool more = (k0 + 16) < K;
        float4 na0, na1, nc0, nc1;
        if (more) {
            na0 = *(const float4*)(arow0 + k0 + 16 + k4);
            na1 = *(const float4*)(arow1 + k0 + 16 + k4);
            nc0 = *(const float4*)(brow0 + k0 + 16 + k4);
            nc1 = *(const float4*)(brow1 + k0 + 16 + k4);
        }
#pragma unroll
        for (int kk = 0; kk < 16; kk++) {
            float4 av0 = *(const float4*)&As[s][kk][ty * 8];
            float4 av1 = *(const float4*)&As[s][kk][ty * 8 + 4];
            float4 bv0 = *(const float4*)&Bs[s][kk][tx * 8];
            float4 bv1 = *(const float4*)&Bs[s][kk][tx * 8 + 4];
            float a[8] = {av0.x, av0.y, av0.z, av0.w, av1.x, av1.y, av1.z, av1.w};
            float b[8] = {bv0.x, bv0.y, bv0.z, bv0.w, bv1.x, bv1.y, bv1.z, bv1.w};
#pragma unroll
            for (int i = 0; i < 8; i++)
#pragma unroll
                for (int j = 0; j < 8; j++) acc[i][j] += a[i] * b[j];
        }
        if (more) {
            const int d = s ^ 1;
            As[d][k4 + 0][lr0] = na0.x; As[d][k4 + 1][lr0] = na0.y; As[d][k4 + 2][lr0] = na0.z; As[d][k4 + 3][lr0] = na0.w;
            As[d][k4 + 0][lr1] = na1.x; As[d][k4 + 1][lr1] = na1.y; As[d][k4 + 2][lr1] = na1.z; As[d][k4 + 3][lr1] = na1.w;
            Bs[d][k4 + 0][lr0] = nc0.x; Bs[d][k4 + 1][lr0] = nc0.y; Bs[d][k4 + 2][lr0] = nc0.z; Bs[d][k4 + 3][lr0] = nc0.w;
            Bs[d][k4 + 0][lr1] = nc1.x; Bs[d][k4 + 1][lr1] = nc1.y; Bs[d][k4 + 2][lr1] = nc1.z; Bs[d][k4 + 3][lr1] = nc1.w;
            __syncthreads();
            s = d;
        }
    }

    float bb[8];
#pragma unroll
    for (int j = 0; j < 8; j++) {
        int n = bn + tx * 8 + j;
        float v = b0 ? b0[n] : 0.f;
        if (b1) v += b1[n];
        bb[j] = v;
    }
#pragma unroll
    for (int i = 0; i < 8; i++) {
        float* crow = C + (size_t)(bm + ty * 8 + i) * N + bn + tx * 8;
        float4 v0, v1;
        v0.x = acc[i][0] + bb[0]; v0.y = acc[i][1] + bb[1];
        v0.z = acc[i][2] + bb[2]; v0.w = acc[i][3] + bb[3];
        v1.x = acc[i][4] + bb[4]; v1.y = acc[i][5] + bb[5];
        v1.z = acc[i][6] + bb[6]; v1.w = acc[i][7] + bb[7];
        *(float4*)(crow) = v0;
        *(float4*)(crow + 4) = v1;
    }
}

// ---------------- cluster LSTM, register-resident W_hh (R10/R14-proven) --------
__global__ void __launch_bounds__(256) __cluster_dims__(CS, 1, 1)
k_lstm(const float* __restrict__ w_hh, const float* __restrict__ h0,
       const float* __restrict__ c0, const int* __restrict__ slen,
       const float* __restrict__ lin_w) {
    __shared__ float Hf[2 * 128 * BPC * 2];   // [buf][kp][b][2]    8 KB
    __shared__ float Gs[4 * BPC * 132];       // [kq][b][132]       8.4 KB

    const int tid = threadIdx.x;
    const uint32_t rank = cl_rank();
    const int b0g = (blockIdx.x >> 3) * BPC;
    const int r0 = tid & 63;            // owns rows r0 (gates 0/1) and r0+64 (gates 2/3)
    const int kq = tid >> 6;            // k-quarter 0..3 (64 k values = 32 pairs)

    // ---- W_hh rows into REGISTERS (loaded once, reused all steps) ------------
    unsigned long long W0[32], W1[32];
    {
        const int g0 = r0 >> 5, j0 = r0 & 31;              // row r0
        const int g1 = (r0 + 64) >> 5, j1 = r0 & 31;       // row r0+64
        const float2* s0 = (const float2*)(w_hh + (size_t)(g0 * H_ + rank * 32 + j0) * H_) + kq * 32;
        const float2* s1 = (const float2*)(w_hh + (size_t)(g1 * H_ + rank * 32 + j1) * H_) + kq * 32;
#pragma unroll
        for (int i = 0; i < 32; i++) {
            float2 a = s0[i]; W0[i] = pk2(a.x, a.y);
            float2 b = s1[i]; W1[i] = pk2(b.x, b.y);
        }
    }
    // ---- init h buffer 0 from h0 ----------------------------------------------
    if (tid < 128) {
#pragma unroll
        for (int b = 0; b < BPC; b++) {
            float2 v = *(const float2*)(h0 + (size_t)(b0g + b) * H_ + 2 * tid);
            Hf[tid * 8 + b * 2 + 0] = v.x;
            Hf[tid * 8 + b * 2 + 1] = v.y;
        }
    }

    // ---- activation ownership (threads 0..127): (bl, jl) ----------------------
    const int bl = tid >> 5, jl = tid & 31;
    const int bg = b0g + bl;
    const int jglob = rank * 32 + jl;
    float c = 0.f, hsum = 0.f;
    int mylen = 0;
    const float* gxp[4];
    if (tid < 128) {
        c = c0[bg * H_ + jglob];
        mylen = slen[bg];
#pragma unroll
        for (int g = 0; g < 4; g++)
            gxp[g] = g_gx + (size_t)bg * T_ * G_ + (size_t)g * H_ + jglob;
    }
    int tmax = 0;
#pragma unroll
    for (int b = 0; b < BPC; b++) tmax = max(tmax, slen[b0g + b]);

    // peer SMEM addresses of the h buffer (for paired DSMEM broadcast of new h)
    const uint32_t h_local = smem_u32(Hf);
    uint32_t peer[CS];
#pragma unroll
    for (int r = 0; r < CS; r++) peer[r] = cl_map(h_local, r);

    __syncthreads();
    cl_arrive();
    // prefetch step 0's input-side gate pre-acts while the barrier settles
    float gx0 = 0.f, gx1 = 0.f, gx2 = 0.f, gx3 = 0.f;
    if (tid < 128) {
        gx0 = __ldg(gxp[0]); gx1 = __ldg(gxp[1]);
        gx2 = __ldg(gxp[2]); gx3 = __ldg(gxp[3]);
    }
    cl_wait();   // all CTAs initialized before any remote traffic

    for (int t = 0; t < tmax; t++) {
        const int cur = t & 1, nxt = cur ^ 1;

        // mini-GEMM: all W from registers, h via broadcast LDS
        unsigned long long a00 = 0ull, a01 = 0ull, a02 = 0ull, a03 = 0ull;
        unsigned long long a10 = 0ull, a11 = 0ull, a12 = 0ull, a13 = 0ull;
        const float* hb = Hf + cur * (128 * BPC * 2) + kq * 32 * 8;
#pragma unroll
        for (int i = 0; i < 32; i++) {
            const ulonglong2* hp = (const ulonglong2*)(hb + i * 8);
            ulonglong2 u01 = hp[0];
            ulonglong2 u23 = hp[1];
            fma2(a00, u01.x, W0[i]); fma2(a01, u01.y, W0[i]);
            fma2(a02, u23.x, W0[i]); fma2(a03, u23.y, W0[i]);
            fma2(a10, u01.x, W1[i]); fma2(a11, u01.y, W1[i]);
            fma2(a12, u23.x, W1[i]); fma2(a13, u23.y, W1[i]);
        }
        {
            float* gs = Gs + kq * (BPC * 132);
            float2 p;
            p = up2(a00); gs[0 * 132 + r0] = p.x + p.y;
            p = up2(a01); gs[1 * 132 + r0] = p.x + p.y;
            p = up2(a02); gs[2 * 132 + r0] = p.x + p.y;
            p = up2(a03); gs[3 * 132 + r0] = p.x + p.y;
            p = up2(a10); gs[0 * 132 + r0 + 64] = p.x + p.y;
            p = up2(a11); gs[1 * 132 + r0 + 64] = p.x + p.y;
            p = up2(a12); gs[2 * 132 + r0 + 64] = p.x + p.y;
            p = up2(a13); gs[3 * 132 + r0 + 64] = p.x + p.y;
        }
        __syncthreads();

        // activations + state update; paired 64-bit broadcast to all cluster CTAs
        if (tid < 128) {
            float gi = gx0, gf = gx1, gg = gx2, go = gx3;
#pragma unroll
            for (int q = 0; q < 4; q++) {
                const float* gsq = Gs + q * (BPC * 132) + bl * 132 + jl;
                gi += gsq[0];
                gf += gsq[32];
                gg += gsq[64];
                go += gsq[96];
            }
            float si = 1.f / (1.f + __expf(-gi));
            float sf = 1.f / (1.f + __expf(-gf));
            float so = 1.f / (1.f + __expf(-go));
            c = sf * c + si * tanhf(gg);
            float h = so * tanhf(c);
            if (t < mylen) hsum += h;
            // lanes (jl even, jl odd) pair up -> one v2.f32 store per peer
            float hpart = __shfl_xor_sync(0xffffffffu, h, 1);
            if ((jl & 1) == 0) {
                const uint32_t off =
                    (uint32_t)(nxt * (128 * BPC * 2) + (jglob >> 1) * 8 + bl * 2) * 4u;
#pragma unroll
                for (int r = 0; r < CS; r++)
                    st_cluster_f32x2(peer[r] + off, h, hpart);
            }
        }
        cl_arrive();
        // overlap next step's gx prefetch with the cluster-barrier wait
        if (tid < 128 && (t + 1 < tmax)) {
            const size_t toff = (size_t)(t + 1) * G_;
            gx0 = __ldg(gxp[0] + toff);
            gx1 = __ldg(gxp[1] + toff);
            gx2 = __ldg(gxp[2] + toff);
            gx3 = __ldg(gxp[3] + toff);
        }
        cl_wait();
    }
    cl_arrive(); cl_wait();   // drain in-flight remote stores before exit

    // ---- masked-sum . lin_w: warp = one batch, lanes = 32 j's -----------------
    if (tid < 128) {
        float v = hsum * lin_w[jglob];
        v += __shfl_xor_sync(0xffffffffu, v, 16);
        v += __shfl_xor_sync(0xffffffffu, v, 8);
        v += __shfl_xor_sync(0xffffffffu, v, 4);
        v += __shfl_xor_sync(0xffffffffu, v, 2);
        v += __shfl_xor_sync(0xffffffffu, v, 1);
        if (jl == 0) g_part[bg][rank] = v;
    }
}

// ---------------- finisher -----------------------------------------------------
__global__ void k_final(const int* __restrict__ slen, const float* __restrict__ lin_b,
                        float* __restrict__ out) {
    int b = threadIdx.x;  // 64
    float s = 0.f;
#pragma unroll
    for (int r = 0; r < CS; r++) s += g_part[b][r];
    float v = s / (float)slen[b] + lin_b[0];
    out[b] = 1.f / (1.f + expf(-v));
}

// ---------------- launch -------------------------------------------------------
extern "C" void kernel_launch(void* const* d_in, const int* in_sizes, int n_in,
                              void* d_out, int out_size) {
    const int*   ipts  = (const int*)d_in[0];
    const int*   slen  = (const int*)d_in[1];
    const float* h0    = (const float*)d_in[2];
    const float* c0    = (const float*)d_in[3];
    const float* emb   = (const float*)d_in[4];
    const float* convw = (const float*)d_in[5];
    const float* convb = (const float*)d_in[6];
    const float* w_ih  = (const float*)d_in[7];
    const float* w_hh  = (const float*)d_in[8];
    const float* b_ih  = (const float*)d_in[9];
    const float* b_hh  = (const float*)d_in[10];
    const float* lin_w = (const float*)d_in[11];
    const float* lin_b = (const float*)d_in[12];
    float* out = (float*)d_out;

    float *p_xemb, *p_conv, *p_gx, *p_wT;
    cudaGetSymbolAddress((void**)&p_xemb, g_xemb);
    cudaGetSymbolAddress((void**)&p_conv, g_conv);
    cudaGetSymbolAddress((void**)&p_gx, g_gx);
    cudaGetSymbolAddress((void**)&p_wT, g_wT);

    // 1) embedding gather (bulk blocks, dead rows skipped)
    k_embed<<<(B_ * S_) / 64, 256>>>(ipts, emb, slen);
    // 2) transpose conv weights to [F][768]
    k_wt<<<(3 * E_ * F_ + 255) / 256, 256>>>(convw);
    // 3) conv as NT GEMM over contiguous 768-float windows (skips t >= len[b])
    {
        dim3 g(F_ / 128, (B_ * T_) / 128);  // (2, 511)
        k_gemm<1><<<g, 256>>>(p_xemb, p_wT, p_conv, B_ * T_, F_, 3 * E_, convb, nullptr, slen);
    }
    // 4) input projection: gates_x = conv_out @ w_ih^T + (b_ih+b_hh) (skips too)
    {
        dim3 g(G_ / 128, (B_ * T_) / 128);  // (8, 511)
        k_gemm<0><<<g, 256>>>(p_conv, w_ih, p_gx, B_ * T_, G_, F_, b_ih, b_hh, slen);
    }
    // 5) cluster LSTM recurrence (W in registers, barrier.cluster, paired stores)
    k_lstm<<<NCLUS * CS, 256>>>(w_hh, h0, c0, slen, lin_w);
    // 6) final: masked mean . linear . sigmoid
    k_final<<<1, 64>>>(slen, lin_b, out);
}

// round 16
// speedup vs baseline: 1.2302x; 1.1932x over previous
#include <cuda_runtime.h>
#include <math.h>
#include <stdint.h>

#define B_ 64
#define S_ 1024
#define T_ 1022
#define E_ 256
#define F_ 256
#define H_ 256
#define G_ 1024
#define CS 8          // cluster size (CTAs per cluster)
#define NCLUS 16      // clusters
#define BPC 4         // batches per cluster

// ---------------- device scratch (allocation-free rule: __device__ globals) ----
__device__ float g_xemb[(size_t)B_ * S_ * E_];      // embedded input
__device__ float g_conv[(size_t)B_ * T_ * F_];      // conv output
__device__ float g_gx[(size_t)B_ * T_ * G_];        // gate pre-acts (input side)
__device__ float g_wT[F_ * 3 * E_];                 // conv_w transposed [F][768]
__device__ float g_part[B_][CS];                    // per-(batch,rank) partial sums

// ---------------- helpers ------------------------------------------------------
__device__ __forceinline__ unsigned long long pk2(float x, float y) {
    unsigned long long r;
    asm("mov.b64 %0, {%1, %2};" : "=l"(r) : "f"(x), "f"(y));
    return r;
}
__device__ __forceinline__ void fma2(unsigned long long& d, unsigned long long a,
                                     unsigned long long b) {
    asm("fma.rn.f32x2 %0, %1, %2, %0;" : "+l"(d) : "l"(a), "l"(b));
}
__device__ __forceinline__ float2 up2(unsigned long long v) {
    float2 r;
    asm("mov.b64 {%0, %1}, %2;" : "=f"(r.x), "=f"(r.y) : "l"(v));
    return r;
}
__device__ __forceinline__ uint32_t smem_u32(const void* p) {
    uint32_t a;
    asm("{ .reg .u64 t; cvta.to.shared.u64 t, %1; cvt.u32.u64 %0, t; }"
        : "=r"(a) : "l"(p));
    return a;
}
__device__ __forceinline__ uint32_t cl_rank() {
    uint32_t r; asm("mov.u32 %0, %%cluster_ctarank;" : "=r"(r)); return r;
}
__device__ __forceinline__ uint32_t cl_map(uint32_t laddr, uint32_t rank) {
    uint32_t r;
    asm("mapa.shared::cluster.u32 %0, %1, %2;" : "=r"(r) : "r"(laddr), "r"(rank));
    return r;
}
__device__ __forceinline__ void st_cluster_f32x2(uint32_t addr, float lo, float hi) {
    asm volatile("st.shared::cluster.v2.f32 [%0], {%1, %2};"
                 :: "r"(addr), "f"(lo), "f"(hi) : "memory");
}
__device__ __forceinline__ void cl_arrive() {
    asm volatile("barrier.cluster.arrive.aligned;" ::: "memory");
}
__device__ __forceinline__ void cl_wait() {
    asm volatile("barrier.cluster.wait.aligned;" ::: "memory");
}
__device__ __forceinline__ uint32_t tf32c(float f) {
    uint32_t u;
    asm("cvt.rna.tf32.f32 %0, %1;" : "=r"(u) : "f"(f));
    return u;
}
__device__ __forceinline__ void mma_tf32(float* c, const uint32_t* a, const uint32_t* b) {
    asm("mma.sync.aligned.m16n8k8.row.col.f32.tf32.tf32.f32 "
        "{%0,%1,%2,%3}, {%4,%5,%6,%7}, {%8,%9}, {%0,%1,%2,%3};"
        : "+f"(c[0]), "+f"(c[1]), "+f"(c[2]), "+f"(c[3])
        : "r"(a[0]), "r"(a[1]), "r"(a[2]), "r"(a[3]), "r"(b[0]), "r"(b[1]));
}

// ---------------- embedding gather (bulk blocks + dead-row skip) ---------------
__global__ void k_embed(const int* __restrict__ ipts, const float* __restrict__ emb,
                        const int* __restrict__ slen) {
    const int base = blockIdx.x * 64;            // 64 rows per block
#pragma unroll
    for (int i = 0; i < 16; i++) {
        int flat = i * 256 + threadIdx.x;        // 0..4095 over 64 rows x 64 f4
        int rl = flat >> 6, c = flat & 63;
        int row = base + rl;
        int b = row >> 10, s = row & 1023;
        if (s < slen[b] + 2) {
            int idx = ipts[row];
            ((float4*)(g_xemb + (size_t)row * E_))[c] =
                ((const float4*)(emb + (size_t)idx * E_))[c];
        }
    }
}

// ---------------- conv_w transpose: [768][256] -> [256][768] ------------------
__global__ void k_wt(const float* __restrict__ conv_w) {
    int i = blockIdx.x * blockDim.x + threadIdx.x;
    if (i < 3 * E_ * F_) {
        int we = i / F_, f = i % F_;
        g_wT[f * (3 * E_) + we] = conv_w[i];
    }
}

// ---------------- NT GEMM via tf32 mma.sync (m16n8k8), 128x128x16 tiles --------
// Staging/skip identical to the proven fp32 kernel; values converted to tf32
// during SMEM store; fp32 accumulate; biases added exactly in epilogue.
// 8 warps: warp w computes C-tile rows (w&3)*32..+32, cols (w>>2)*64..+64.
// MODE 0: A row m at A + m*K. MODE 1: conv windows (contiguous 768 floats).
template <int MODE>
__global__ void __launch_bounds__(256, 2)
k_gemm(const float* __restrict__ A, const float* __restrict__ Bm,
       float* __restrict__ C, int M, int N, int K,
       const float* __restrict__ b0, const float* __restrict__ b1,
       const int* __restrict__ slen) {
    const int bm = blockIdx.y * 128;
    {
        int bfirst = bm / T_;
        int tfirst = bm - bfirst * T_;
        int blast = (bm + 127) / T_;
        if (blast == bfirst && tfirst >= slen[bfirst]) return;
    }

    __shared__ uint32_t As[16][136];   // tf32 bits, [k][m]
    __shared__ uint32_t Bs[16][136];   // tf32 bits, [k][n]
    const int tid = threadIdx.x;
    const int bn = blockIdx.x * 128;

    const int lr0 = (tid >> 2), lr1 = lr0 + 64;
    const int k4 = (tid & 3) * 4;

    const float* arow0;
    const float* arow1;
    if (MODE == 0) {
        arow0 = A + (size_t)(bm + lr0) * K;
        arow1 = A + (size_t)(bm + lr1) * K;
    } else {
        unsigned r0 = bm + lr0, r1 = bm + lr1;
        arow0 = A + (size_t)(r0 / T_) * (S_ * E_) + (size_t)(r0 % T_) * E_;
        arow1 = A + (size_t)(r1 / T_) * (S_ * E_) + (size_t)(r1 % T_) * E_;
    }
    const float* brow0 = Bm + (size_t)(bn + lr0) * K;
    const float* brow1 = Bm + (size_t)(bn + lr1) * K;

    const int wid = tid >> 5, lane = tid & 31;
    const int wm = (wid & 3) * 32;     // warp row offset in tile
    const int wn = (wid >> 2) * 64;    // warp col offset in tile
    const int lr = lane >> 2;          // 0..7
    const int lk = lane & 3;           // 0..3

    float acc[2][8][4];
#pragma unroll
    for (int t = 0; t < 2; t++)
#pragma unroll
        for (int u = 0; u < 8; u++)
#pragma unroll
            for (int v = 0; v < 4; v++) acc[t][u][v] = 0.f;

    for (int k0 = 0; k0 < K; k0 += 16) {
        float4 a0 = *(const float4*)(arow0 + k0 + k4);
        float4 a1 = *(const float4*)(arow1 + k0 + k4);
        float4 c0 = *(const float4*)(brow0 + k0 + k4);
        float4 c1 = *(const float4*)(brow1 + k0 + k4);
        __syncthreads();
        As[k4 + 0][lr0] = tf32c(a0.x); As[k4 + 1][lr0] = tf32c(a0.y);
        As[k4 + 2][lr0] = tf32c(a0.z); As[k4 + 3][lr0] = tf32c(a0.w);
        As[k4 + 0][lr1] = tf32c(a1.x); As[k4 + 1][lr1] = tf32c(a1.y);
        As[k4 + 2][lr1] = tf32c(a1.z); As[k4 + 3][lr1] = tf32c(a1.w);
        Bs[k4 + 0][lr0] = tf32c(c0.x); Bs[k4 + 1][lr0] = tf32c(c0.y);
        Bs[k4 + 2][lr0] = tf32c(c0.z); Bs[k4 + 3][lr0] = tf32c(c0.w);
        Bs[k4 + 0][lr1] = tf32c(c1.x); Bs[k4 + 1][lr1] = tf32c(c1.y);
        Bs[k4 + 2][lr1] = tf32c(c1.z); Bs[k4 + 3][lr1] = tf32c(c1.w);
        __syncthreads();
#pragma unroll
        for (int s = 0; s < 2; s++) {
            const int kb = s * 8;
            uint32_t af[2][4];
#pragma unroll
            for (int t = 0; t < 2; t++) {
                const int row = wm + t * 16 + lr;
                af[t][0] = As[kb + lk][row];
                af[t][1] = As[kb + lk][row + 8];
                af[t][2] = As[kb + lk + 4][row];
                af[t][3] = As[kb + lk + 4][row + 8];
            }
            uint32_t bf[8][2];
#pragma unroll
            for (int u = 0; u < 8; u++) {
                const int col = wn + u * 8 + lr;
                bf[u][0] = Bs[kb + lk][col];
                bf[u][1] = Bs[kb + lk + 4][col];
            }
#pragma unroll
            for (int t = 0; t < 2; t++)
#pragma unroll
                for (int u = 0; u < 8; u++) mma_tf32(acc[t][u], af[t], bf[u]);
        }
    }

    // epilogue: add bias (exact fp32), write float2 per fragment row
#pragma unroll
    for (int t = 0; t < 2; t++) {
        const int row = bm + wm + t * 16 + lr;
#pragma unroll
        for (int u = 0; u < 8; u++) {
            const int col = bn + wn + u * 8 + 2 * lk;
            float bias0 = b0 ? b0[col] : 0.f;
            float bias1 = b0 ? b0[col + 1] : 0.f;
            if (b1) { bias0 += b1[col]; bias1 += b1[col + 1]; }
            float2 v0 = {acc[t][u][0] + bias0, acc[t][u][1] + bias1};
            float2 v1 = {acc[t][u][2] + bias0, acc[t][u][3] + bias1};
            *(float2*)(C + (size_t)row * N + col) = v0;
            *(float2*)(C + (size_t)(row + 8) * N + col) = v1;
        }
    }
}

// ---------------- cluster LSTM, register-resident W_hh (R15-proven, unchanged) -
__global__ void __launch_bounds__(256) __cluster_dims__(CS, 1, 1)
k_lstm(const float* __restrict__ w_hh, const float* __restrict__ h0,
       const float* __restrict__ c0, const int* __restrict__ slen,
       const float* __restrict__ lin_w) {
    __shared__ float Hf[2 * 128 * BPC * 2];   // [buf][kp][b][2]    8 KB
    __shared__ float Gs[4 * BPC * 132];       // [kq][b][132]       8.4 KB

    const int tid = threadIdx.x;
    const uint32_t rank = cl_rank();
    const int b0g = (blockIdx.x >> 3) * BPC;
    const int r0 = tid & 63;            // owns rows r0 (gates 0/1) and r0+64 (gates 2/3)
    const int kq = tid >> 6;            // k-quarter 0..3 (64 k values = 32 pairs)

    // ---- W_hh rows into REGISTERS (loaded once, reused all steps) ------------
    unsigned long long W0[32], W1[32];
    {
        const int g0 = r0 >> 5, j0 = r0 & 31;              // row r0
        const int g1 = (r0 + 64) >> 5, j1 = r0 & 31;       // row r0+64
        const float2* s0 = (const float2*)(w_hh + (size_t)(g0 * H_ + rank * 32 + j0) * H_) + kq * 32;
        const float2* s1 = (const float2*)(w_hh + (size_t)(g1 * H_ + rank * 32 + j1) * H_) + kq * 32;
#pragma unroll
        for (int i = 0; i < 32; i++) {
            float2 a = s0[i]; W0[i] = pk2(a.x, a.y);
            float2 b = s1[i]; W1[i] = pk2(b.x, b.y);
        }
    }
    // ---- init h buffer 0 from h0 ----------------------------------------------
    if (tid < 128) {
#pragma unroll
        for (int b = 0; b < BPC; b++) {
            float2 v = *(const float2*)(h0 + (size_t)(b0g + b) * H_ + 2 * tid);
            Hf[tid * 8 + b * 2 + 0] = v.x;
            Hf[tid * 8 + b * 2 + 1] = v.y;
        }
    }

    // ---- activation ownership (threads 0..127): (bl, jl) ----------------------
    const int bl = tid >> 5, jl = tid & 31;
    const int bg = b0g + bl;
    const int jglob = rank * 32 + jl;
    float c = 0.f, hsum = 0.f;
    int mylen = 0;
    const float* gxp[4];
    if (tid < 128) {
        c = c0[bg * H_ + jglob];
        mylen = slen[bg];
#pragma unroll
        for (int g = 0; g < 4; g++)
            gxp[g] = g_gx + (size_t)bg * T_ * G_ + (size_t)g * H_ + jglob;
    }
    int tmax = 0;
#pragma unroll
    for (int b = 0; b < BPC; b++) tmax = max(tmax, slen[b0g + b]);

    // peer SMEM addresses of the h buffer (for paired DSMEM broadcast of new h)
    const uint32_t h_local = smem_u32(Hf);
    uint32_t peer[CS];
#pragma unroll
    for (int r = 0; r < CS; r++) peer[r] = cl_map(h_local, r);

    __syncthreads();
    cl_arrive();
    // prefetch step 0's input-side gate pre-acts while the barrier settles
    float gx0 = 0.f, gx1 = 0.f, gx2 = 0.f, gx3 = 0.f;
    if (tid < 128) {
        gx0 = __ldg(gxp[0]); gx1 = __ldg(gxp[1]);
        gx2 = __ldg(gxp[2]); gx3 = __ldg(gxp[3]);
    }
    cl_wait();   // all CTAs initialized before any remote traffic

    for (int t = 0; t < tmax; t++) {
        const int cur = t & 1, nxt = cur ^ 1;

        // mini-GEMM: all W from registers, h via broadcast LDS
        unsigned long long a00 = 0ull, a01 = 0ull, a02 = 0ull, a03 = 0ull;
        unsigned long long a10 = 0ull, a11 = 0ull, a12 = 0ull, a13 = 0ull;
        const float* hb = Hf + cur * (128 * BPC * 2) + kq * 32 * 8;
#pragma unroll
        for (int i = 0; i < 32; i++) {
            const ulonglong2* hp = (const ulonglong2*)(hb + i * 8);
            ulonglong2 u01 = hp[0];
            ulonglong2 u23 = hp[1];
            fma2(a00, u01.x, W0[i]); fma2(a01, u01.y, W0[i]);
            fma2(a02, u23.x, W0[i]); fma2(a03, u23.y, W0[i]);
            fma2(a10, u01.x, W1[i]); fma2(a11, u01.y, W1[i]);
            fma2(a12, u23.x, W1[i]); fma2(a13, u23.y, W1[i]);
        }
        {
            float* gs = Gs + kq * (BPC * 132);
            float2 p;
            p = up2(a00); gs[0 * 132 + r0] = p.x + p.y;
            p = up2(a01); gs[1 * 132 + r0] = p.x + p.y;
            p = up2(a02); gs[2 * 132 + r0] = p.x + p.y;
            p = up2(a03); gs[3 * 132 + r0] = p.x + p.y;
            p = up2(a10); gs[0 * 132 + r0 + 64] = p.x + p.y;
            p = up2(a11); gs[1 * 132 + r0 + 64] = p.x + p.y;
            p = up2(a12); gs[2 * 132 + r0 + 64] = p.x + p.y;
            p = up2(a13); gs[3 * 132 + r0 + 64] = p.x + p.y;
        }
        __syncthreads();

        // activations + state update; paired 64-bit broadcast to all cluster CTAs
        if (tid < 128) {
            float gi = gx0, gf = gx1, gg = gx2, go = gx3;
#pragma unroll
            for (int q = 0; q < 4; q++) {
                const float* gsq = Gs + q * (BPC * 132) + bl * 132 + jl;
                gi += gsq[0];
                gf += gsq[32];
                gg += gsq[64];
                go += gsq[96];
            }
            float si = 1.f / (1.f + __expf(-gi));
            float sf = 1.f / (1.f + __expf(-gf));
            float so = 1.f / (1.f + __expf(-go));
            c = sf * c + si * tanhf(gg);
            float h = so * tanhf(c);
            if (t < mylen) hsum += h;
            // lanes (jl even, jl odd) pair up -> one v2.f32 store per peer
            float hpart = __shfl_xor_sync(0xffffffffu, h, 1);
            if ((jl & 1) == 0) {
                const uint32_t off =
                    (uint32_t)(nxt * (128 * BPC * 2) + (jglob >> 1) * 8 + bl * 2) * 4u;
#pragma unroll
                for (int r = 0; r < CS; r++)
                    st_cluster_f32x2(peer[r] + off, h, hpart);
            }
        }
        cl_arrive();
        // overlap next step's gx prefetch with the cluster-barrier wait
        if (tid < 128 && (t + 1 < tmax)) {
            const size_t toff = (size_t)(t + 1) * G_;
            gx0 = __ldg(gxp[0] + toff);
            gx1 = __ldg(gxp[1] + toff);
            gx2 = __ldg(gxp[2] + toff);
            gx3 = __ldg(gxp[3] + toff);
        }
        cl_wait();
    }
    cl_arrive(); cl_wait();   // drain in-flight remote stores before exit

    // ---- masked-sum . lin_w: warp = one batch, lanes = 32 j's -----------------
    if (tid < 128) {
        float v = hsum * lin_w[jglob];
        v += __shfl_xor_sync(0xffffffffu, v, 16);
        v += __shfl_xor_sync(0xffffffffu, v, 8);
        v += __shfl_xor_sync(0xffffffffu, v, 4);
        v += __shfl_xor_sync(0xffffffffu, v, 2);
        v += __shfl_xor_sync(0xffffffffu, v, 1);
        if (jl == 0) g_part[bg][rank] = v;
    }
}

// ---------------- finisher -----------------------------------------------------
__global__ void k_final(const int* __restrict__ slen, const float* __restrict__ lin_b,
                        float* __restrict__ out) {
    int b = threadIdx.x;  // 64
    float s = 0.f;
#pragma unroll
    for (int r = 0; r < CS; r++) s += g_part[b][r];
    float v = s / (float)slen[b] + lin_b[0];
    out[b] = 1.f / (1.f + expf(-v));
}

// ---------------- launch -------------------------------------------------------
extern "C" void kernel_launch(void* const* d_in, const int* in_sizes, int n_in,
                              void* d_out, int out_size) {
    const int*   ipts  = (const int*)d_in[0];
    const int*   slen  = (const int*)d_in[1];
    const float* h0    = (const float*)d_in[2];
    const float* c0    = (const float*)d_in[3];
    const float* emb   = (const float*)d_in[4];
    const float* convw = (const float*)d_in[5];
    const float* convb = (const float*)d_in[6];
    const float* w_ih  = (const float*)d_in[7];
    const float* w_hh  = (const float*)d_in[8];
    const float* b_ih  = (const float*)d_in[9];
    const float* b_hh  = (const float*)d_in[10];
    const float* lin_w = (const float*)d_in[11];
    const float* lin_b = (const float*)d_in[12];
    float* out = (float*)d_out;

    float *p_xemb, *p_conv, *p_gx, *p_wT;
    cudaGetSymbolAddress((void**)&p_xemb, g_xemb);
    cudaGetSymbolAddress((void**)&p_conv, g_conv);
    cudaGetSymbolAddress((void**)&p_gx, g_gx);
    cudaGetSymbolAddress((void**)&p_wT, g_wT);

    // 1) embedding gather (bulk blocks, dead rows skipped)
    k_embed<<<(B_ * S_) / 64, 256>>>(ipts, emb, slen);
    // 2) transpose conv weights to [F][768]
    k_wt<<<(3 * E_ * F_ + 255) / 256, 256>>>(convw);
    // 3) conv as tf32-MMA NT GEMM over contiguous 768-float windows (+ skip)
    {
        dim3 g(F_ / 128, (B_ * T_) / 128);  // (2, 511)
        k_gemm<1><<<g, 256>>>(p_xemb, p_wT, p_conv, B_ * T_, F_, 3 * E_, convb, nullptr, slen);
    }
    // 4) input projection via tf32 MMA: gates_x = conv @ w_ih^T + bias (+ skip)
    {
        dim3 g(G_ / 128, (B_ * T_) / 128);  // (8, 511)
        k_gemm<0><<<g, 256>>>(p_conv, w_ih, p_gx, B_ * T_, G_, F_, b_ih, b_hh, slen);
    }
    // 5) cluster LSTM recurrence (W in registers, barrier.cluster, paired stores)
    k_lstm<<<NCLUS * CS, 256>>>(w_hh, h0, c0, slen, lin_w);
    // 6) final: masked mean . linear . sigmoid
    k_final<<<1, 64>>>(slen, lin_b, out);
}

// round 17
// speedup vs baseline: 1.2343x; 1.0034x over previous
#include <cuda_runtime.h>
#include <math.h>
#include <stdint.h>

#define B_ 64
#define S_ 1024
#define T_ 1022
#define E_ 256
#define F_ 256
#define H_ 256
#define G_ 1024
#define CS 8          // cluster size (CTAs per cluster)
#define NCLUS 16      // clusters
#define BPC 4         // batches per cluster

// ---------------- device scratch (allocation-free rule: __device__ globals) ----
__device__ float g_xemb[(size_t)B_ * S_ * E_];      // embedded input
__device__ float g_conv[(size_t)B_ * T_ * F_];      // conv output
__device__ float g_gx[(size_t)B_ * T_ * G_];        // gate pre-acts (input side)
__device__ float g_wT[F_ * 3 * E_];                 // conv_w transposed [F][768]
__device__ float g_part[B_][CS];                    // per-(batch,rank) partial sums

// ---------------- helpers ------------------------------------------------------
__device__ __forceinline__ unsigned long long pk2(float x, float y) {
    unsigned long long r;
    asm("mov.b64 %0, {%1, %2};" : "=l"(r) : "f"(x), "f"(y));
    return r;
}
__device__ __forceinline__ void fma2(unsigned long long& d, unsigned long long a,
                                     unsigned long long b) {
    asm("fma.rn.f32x2 %0, %1, %2, %0;" : "+l"(d) : "l"(a), "l"(b));
}
__device__ __forceinline__ float2 up2(unsigned long long v) {
    float2 r;
    asm("mov.b64 {%0, %1}, %2;" : "=f"(r.x), "=f"(r.y) : "l"(v));
    return r;
}
__device__ __forceinline__ uint32_t smem_u32(const void* p) {
    uint32_t a;
    asm("{ .reg .u64 t; cvta.to.shared.u64 t, %1; cvt.u32.u64 %0, t; }"
        : "=r"(a) : "l"(p));
    return a;
}
__device__ __forceinline__ uint32_t cl_rank() {
    uint32_t r; asm("mov.u32 %0, %%cluster_ctarank;" : "=r"(r)); return r;
}
__device__ __forceinline__ uint32_t cl_map(uint32_t laddr, uint32_t rank) {
    uint32_t r;
    asm("mapa.shared::cluster.u32 %0, %1, %2;" : "=r"(r) : "r"(laddr), "r"(rank));
    return r;
}
__device__ __forceinline__ void st_cluster_f32x2(uint32_t addr, float lo, float hi) {
    asm volatile("st.shared::cluster.v2.f32 [%0], {%1, %2};"
                 :: "r"(addr), "f"(lo), "f"(hi) : "memory");
}
__device__ __forceinline__ void cl_arrive() {
    asm volatile("barrier.cluster.arrive.aligned;" ::: "memory");
}
__device__ __forceinline__ void cl_wait() {
    asm volatile("barrier.cluster.wait.aligned;" ::: "memory");
}
__device__ __forceinline__ uint32_t tf32c(float f) {
    uint32_t u;
    asm("cvt.rna.tf32.f32 %0, %1;" : "=r"(u) : "f"(f));
    return u;
}
__device__ __forceinline__ void mma_tf32(float* c, const uint32_t* a, const uint32_t* b) {
    asm("mma.sync.aligned.m16n8k8.row.col.f32.tf32.tf32.f32 "
        "{%0,%1,%2,%3}, {%4,%5,%6,%7}, {%8,%9}, {%0,%1,%2,%3};"
        : "+f"(c[0]), "+f"(c[1]), "+f"(c[2]), "+f"(c[3])
        : "r"(a[0]), "r"(a[1]), "r"(a[2]), "r"(a[3]), "r"(b[0]), "r"(b[1]));
}

// ---------------- embedding gather (bulk blocks + dead-row skip) ---------------
__global__ void k_embed(const int* __restrict__ ipts, const float* __restrict__ emb,
                        const int* __restrict__ slen) {
    const int base = blockIdx.x * 64;            // 64 rows per block
#pragma unroll
    for (int i = 0; i < 16; i++) {
        int flat = i * 256 + threadIdx.x;        // 0..4095 over 64 rows x 64 f4
        int rl = flat >> 6, c = flat & 63;
        int row = base + rl;
        int b = row >> 10, s = row & 1023;
        if (s < slen[b] + 2) {
            int idx = ipts[row];
            ((float4*)(g_xemb + (size_t)row * E_))[c] =
                ((const float4*)(emb + (size_t)idx * E_))[c];
        }
    }
}

// ---------------- conv_w transpose: [768][256] -> [256][768] ------------------
__global__ void k_wt(const float* __restrict__ conv_w) {
    int i = blockIdx.x * blockDim.x + threadIdx.x;
    if (i < 3 * E_ * F_) {
        int we = i / F_, f = i % F_;
        g_wT[f * (3 * E_) + we] = conv_w[i];
    }
}

// ---------------- NT GEMM via tf32 mma.sync, 128x128x16, double-buffered -------
// Staging/skip identical to R16; NEW: 2-stage SMEM so the ~300-577cyc global
// load latency of tile k+1 hides under tile k's LDS+MMA compute (gemm was
// latency-bound at issue=23.6%). fp32 accumulate; exact fp32 bias epilogue.
// 8 warps: warp w computes C-tile rows (w&3)*32..+32, cols (w>>2)*64..+64.
// MODE 0: A row m at A + m*K. MODE 1: conv windows (contiguous 768 floats).
template <int MODE>
__global__ void __launch_bounds__(256, 2)
k_gemm(const float* __restrict__ A, const float* __restrict__ Bm,
       float* __restrict__ C, int M, int N, int K,
       const float* __restrict__ b0, const float* __restrict__ b1,
       const int* __restrict__ slen) {
    const int bm = blockIdx.y * 128;
    {
        int bfirst = bm / T_;
        int tfirst = bm - bfirst * T_;
        int blast = (bm + 127) / T_;
        if (blast == bfirst && tfirst >= slen[bfirst]) return;
    }

    __shared__ uint32_t As[2][16][136];   // tf32 bits, [stage][k][m]
    __shared__ uint32_t Bs[2][16][136];   // tf32 bits, [stage][k][n]
    const int tid = threadIdx.x;
    const int bn = blockIdx.x * 128;

    const int lr0 = (tid >> 2), lr1 = lr0 + 64;
    const int k4 = (tid & 3) * 4;

    const float* arow0;
    const float* arow1;
    if (MODE == 0) {
        arow0 = A + (size_t)(bm + lr0) * K;
        arow1 = A + (size_t)(bm + lr1) * K;
    } else {
        unsigned r0 = bm + lr0, r1 = bm + lr1;
        arow0 = A + (size_t)(r0 / T_) * (S_ * E_) + (size_t)(r0 % T_) * E_;
        arow1 = A + (size_t)(r1 / T_) * (S_ * E_) + (size_t)(r1 % T_) * E_;
    }
    const float* brow0 = Bm + (size_t)(bn + lr0) * K;
    const float* brow1 = Bm + (size_t)(bn + lr1) * K;

    const int wid = tid >> 5, lane = tid & 31;
    const int wm = (wid & 3) * 32;     // warp row offset in tile
    const int wn = (wid >> 2) * 64;    // warp col offset in tile
    const int lr = lane >> 2;          // 0..7
    const int lk = lane & 3;           // 0..3

    float acc[2][8][4];
#pragma unroll
    for (int t = 0; t < 2; t++)
#pragma unroll
        for (int u = 0; u < 8; u++)
#pragma unroll
            for (int v = 0; v < 4; v++) acc[t][u][v] = 0.f;

    // prologue: fill stage 0
    {
        float4 a0 = *(const float4*)(arow0 + k4);
        float4 a1 = *(const float4*)(arow1 + k4);
        float4 c0 = *(const float4*)(brow0 + k4);
        float4 c1 = *(const float4*)(brow1 + k4);
        As[0][k4 + 0][lr0] = tf32c(a0.x); As[0][k4 + 1][lr0] = tf32c(a0.y);
        As[0][k4 + 2][lr0] = tf32c(a0.z); As[0][k4 + 3][lr0] = tf32c(a0.w);
        As[0][k4 + 0][lr1] = tf32c(a1.x); As[0][k4 + 1][lr1] = tf32c(a1.y);
        As[0][k4 + 2][lr1] = tf32c(a1.z); As[0][k4 + 3][lr1] = tf32c(a1.w);
        Bs[0][k4 + 0][lr0] = tf32c(c0.x); Bs[0][k4 + 1][lr0] = tf32c(c0.y);
        Bs[0][k4 + 2][lr0] = tf32c(c0.z); Bs[0][k4 + 3][lr0] = tf32c(c0.w);
        Bs[0][k4 + 0][lr1] = tf32c(c1.x); Bs[0][k4 + 1][lr1] = tf32c(c1.y);
        Bs[0][k4 + 2][lr1] = tf32c(c1.z); Bs[0][k4 + 3][lr1] = tf32c(c1.w);
    }
    __syncthreads();

    int sb = 0;
    for (int k0 = 0; k0 < K; k0 += 16) {
        const bool more = (k0 + 16) < K;
        float4 na0, na1, nc0, nc1;
        if (more) {
            na0 = *(const float4*)(arow0 + k0 + 16 + k4);
            na1 = *(const float4*)(arow1 + k0 + 16 + k4);
            nc0 = *(const float4*)(brow0 + k0 + 16 + k4);
            nc1 = *(const float4*)(brow1 + k0 + 16 + k4);
        }
#pragma unroll
        for (int s = 0; s < 2; s++) {
            const int kb = s * 8;
            uint32_t af[2][4];
#pragma unroll
            for (int t = 0; t < 2; t++) {
                const int row = wm + t * 16 + lr;
                af[t][0] = As[sb][kb + lk][row];
                af[t][1] = As[sb][kb + lk][row + 8];
                af[t][2] = As[sb][kb + lk + 4][row];
                af[t][3] = As[sb][kb + lk + 4][row + 8];
            }
            uint32_t bf[8][2];
#pragma unroll
            for (int u = 0; u < 8; u++) {
                const int col = wn + u * 8 + lr;
                bf[u][0] = Bs[sb][kb + lk][col];
                bf[u][1] = Bs[sb][kb + lk + 4][col];
            }
#pragma unroll
            for (int t = 0; t < 2; t++)
#pragma unroll
                for (int u = 0; u < 8; u++) mma_tf32(acc[t][u], af[t], bf[u]);
        }
        if (more) {
            const int d = sb ^ 1;
            As[d][k4 + 0][lr0] = tf32c(na0.x); As[d][k4 + 1][lr0] = tf32c(na0.y);
            As[d][k4 + 2][lr0] = tf32c(na0.z); As[d][k4 + 3][lr0] = tf32c(na0.w);
            As[d][k4 + 0][lr1] = tf32c(na1.x); As[d][k4 + 1][lr1] = tf32c(na1.y);
            As[d][k4 + 2][lr1] = tf32c(na1.z); As[d][k4 + 3][lr1] = tf32c(na1.w);
            Bs[d][k4 + 0][lr0] = tf32c(nc0.x); Bs[d][k4 + 1][lr0] = tf32c(nc0.y);
            Bs[d][k4 + 2][lr0] = tf32c(nc0.z); Bs[d][k4 + 3][lr0] = tf32c(nc0.w);
            Bs[d][k4 + 0][lr1] = tf32c(nc1.x); Bs[d][k4 + 1][lr1] = tf32c(nc1.y);
            Bs[d][k4 + 2][lr1] = tf32c(nc1.z); Bs[d][k4 + 3][lr1] = tf32c(nc1.w);
            __syncthreads();
            sb = d;
        }
    }

    // epilogue: add bias (exact fp32), write float2 per fragment row
#pragma unroll
    for (int t = 0; t < 2; t++) {
        const int row = bm + wm + t * 16 + lr;
#pragma unroll
        for (int u = 0; u < 8; u++) {
            const int col = bn + wn + u * 8 + 2 * lk;
            float bias0 = b0 ? b0[col] : 0.f;
            float bias1 = b0 ? b0[col + 1] : 0.f;
            if (b1) { bias0 += b1[col]; bias1 += b1[col + 1]; }
            float2 v0 = {acc[t][u][0] + bias0, acc[t][u][1] + bias1};
            float2 v1 = {acc[t][u][2] + bias0, acc[t][u][3] + bias1};
            *(float2*)(C + (size_t)row * N + col) = v0;
            *(float2*)(C + (size_t)(row + 8) * N + col) = v1;
        }
    }
}

// ---------------- cluster LSTM, register-resident W_hh (R16-proven, unchanged) -
__global__ void __launch_bounds__(256) __cluster_dims__(CS, 1, 1)
k_lstm(const float* __restrict__ w_hh, const float* __restrict__ h0,
       const float* __restrict__ c0, const int* __restrict__ slen,
       const float* __restrict__ lin_w) {
    __shared__ float Hf[2 * 128 * BPC * 2];   // [buf][kp][b][2]    8 KB
    __shared__ float Gs[4 * BPC * 132];       // [kq][b][132]       8.4 KB

    const int tid = threadIdx.x;
    const uint32_t rank = cl_rank();
    const int b0g = (blockIdx.x >> 3) * BPC;
    const int r0 = tid & 63;            // owns rows r0 (gates 0/1) and r0+64 (gates 2/3)
    const int kq = tid >> 6;            // k-quarter 0..3 (64 k values = 32 pairs)

    // ---- W_hh rows into REGISTERS (loaded once, reused all steps) ------------
    unsigned long long W0[32], W1[32];
    {
        const int g0 = r0 >> 5, j0 = r0 & 31;              // row r0
        const int g1 = (r0 + 64) >> 5, j1 = r0 & 31;       // row r0+64
        const float2* s0 = (const float2*)(w_hh + (size_t)(g0 * H_ + rank * 32 + j0) * H_) + kq * 32;
        const float2* s1 = (const float2*)(w_hh + (size_t)(g1 * H_ + rank * 32 + j1) * H_) + kq * 32;
#pragma unroll
        for (int i = 0; i < 32; i++) {
            float2 a = s0[i]; W0[i] = pk2(a.x, a.y);
            float2 b = s1[i]; W1[i] = pk2(b.x, b.y);
        }
    }
    // ---- init h buffer 0 from h0 ----------------------------------------------
    if (tid < 128) {
#pragma unroll
        for (int b = 0; b < BPC; b++) {
            float2 v = *(const float2*)(h0 + (size_t)(b0g + b) * H_ + 2 * tid);
            Hf[tid * 8 + b * 2 + 0] = v.x;
            Hf[tid * 8 + b * 2 + 1] = v.y;
        }
    }

    // ---- activation ownership (threads 0..127): (bl, jl) ----------------------
    const int bl = tid >> 5, jl = tid & 31;
    const int bg = b0g + bl;
    const int jglob = rank * 32 + jl;
    float c = 0.f, hsum = 0.f;
    int mylen = 0;
    const float* gxp[4];
    if (tid < 128) {
        c = c0[bg * H_ + jglob];
        mylen = slen[bg];
#pragma unroll
        for (int g = 0; g < 4; g++)
            gxp[g] = g_gx + (size_t)bg * T_ * G_ + (size_t)g * H_ + jglob;
    }
    int tmax = 0;
#pragma unroll
    for (int b = 0; b < BPC; b++) tmax = max(tmax, slen[b0g + b]);

    // peer SMEM addresses of the h buffer (for paired DSMEM broadcast of new h)
    const uint32_t h_local = smem_u32(Hf);
    uint32_t peer[CS];
#pragma unroll
    for (int r = 0; r < CS; r++) peer[r] = cl_map(h_local, r);

    __syncthreads();
    cl_arrive();
    // prefetch step 0's input-side gate pre-acts while the barrier settles
    float gx0 = 0.f, gx1 = 0.f, gx2 = 0.f, gx3 = 0.f;
    if (tid < 128) {
        gx0 = __ldg(gxp[0]); gx1 = __ldg(gxp[1]);
        gx2 = __ldg(gxp[2]); gx3 = __ldg(gxp[3]);
    }
    cl_wait();   // all CTAs initialized before any remote traffic

    for (int t = 0; t < tmax; t++) {
        const int cur = t & 1, nxt = cur ^ 1;

        // mini-GEMM: all W from registers, h via broadcast LDS
        unsigned long long a00 = 0ull, a01 = 0ull, a02 = 0ull, a03 = 0ull;
        unsigned long long a10 = 0ull, a11 = 0ull, a12 = 0ull, a13 = 0ull;
        const float* hb = Hf + cur * (128 * BPC * 2) + kq * 32 * 8;
#pragma unroll
        for (int i = 0; i < 32; i++) {
            const ulonglong2* hp = (const ulonglong2*)(hb + i * 8);
            ulonglong2 u01 = hp[0];
            ulonglong2 u23 = hp[1];
            fma2(a00, u01.x, W0[i]); fma2(a01, u01.y, W0[i]);
            fma2(a02, u23.x, W0[i]); fma2(a03, u23.y, W0[i]);
            fma2(a10, u01.x, W1[i]); fma2(a11, u01.y, W1[i]);
            fma2(a12, u23.x, W1[i]); fma2(a13, u23.y, W1[i]);
        }
        {
            float* gs = Gs + kq * (BPC * 132);
            float2 p;
            p = up2(a00); gs[0 * 132 + r0] = p.x + p.y;
            p = up2(a01); gs[1 * 132 + r0] = p.x + p.y;
            p = up2(a02); gs[2 * 132 + r0] = p.x + p.y;
            p = up2(a03); gs[3 * 132 + r0] = p.x + p.y;
            p = up2(a10); gs[0 * 132 + r0 + 64] = p.x + p.y;
            p = up2(a11); gs[1 * 132 + r0 + 64] = p.x + p.y;
            p = up2(a12); gs[2 * 132 + r0 + 64] = p.x + p.y;
            p = up2(a13); gs[3 * 132 + r0 + 64] = p.x + p.y;
        }
        __syncthreads();

        // activations + state update; paired 64-bit broadcast to all cluster CTAs
        if (tid < 128) {
            float gi = gx0, gf = gx1, gg = gx2, go = gx3;
#pragma unroll
            for (int q = 0; q < 4; q++) {
                const float* gsq = Gs + q * (BPC * 132) + bl * 132 + jl;
                gi += gsq[0];
                gf += gsq[32];
                gg += gsq[64];
                go += gsq[96];
            }
            float si = 1.f / (1.f + __expf(-gi));
            float sf = 1.f / (1.f + __expf(-gf));
            float so = 1.f / (1.f + __expf(-go));
            c = sf * c + si * tanhf(gg);
            float h = so * tanhf(c);
            if (t < mylen) hsum += h;
            // lanes (jl even, jl odd) pair up -> one v2.f32 store per peer
            float hpart = __shfl_xor_sync(0xffffffffu, h, 1);
            if ((jl & 1) == 0) {
                const uint32_t off =
                    (uint32_t)(nxt * (128 * BPC * 2) + (jglob >> 1) * 8 + bl * 2) * 4u;
#pragma unroll
                for (int r = 0; r < CS; r++)
                    st_cluster_f32x2(peer[r] + off, h, hpart);
            }
        }
        cl_arrive();
        // overlap next step's gx prefetch with the cluster-barrier wait
        if (tid < 128 && (t + 1 < tmax)) {
            const size_t toff = (size_t)(t + 1) * G_;
            gx0 = __ldg(gxp[0] + toff);
            gx1 = __ldg(gxp[1] + toff);
            gx2 = __ldg(gxp[2] + toff);
            gx3 = __ldg(gxp[3] + toff);
        }
        cl_wait();
    }
    cl_arrive(); cl_wait();   // drain in-flight remote stores before exit

    // ---- masked-sum . lin_w: warp = one batch, lanes = 32 j's -----------------
    if (tid < 128) {
        float v = hsum * lin_w[jglob];
        v += __shfl_xor_sync(0xffffffffu, v, 16);
        v += __shfl_xor_sync(0xffffffffu, v, 8);
        v += __shfl_xor_sync(0xffffffffu, v, 4);
        v += __shfl_xor_sync(0xffffffffu, v, 2);
        v += __shfl_xor_sync(0xffffffffu, v, 1);
        if (jl == 0) g_part[bg][rank] = v;
    }
}

// ---------------- finisher -----------------------------------------------------
__global__ void k_final(const int* __restrict__ slen, const float* __restrict__ lin_b,
                        float* __restrict__ out) {
    int b = threadIdx.x;  // 64
    float s = 0.f;
#pragma unroll
    for (int r = 0; r < CS; r++) s += g_part[b][r];
    float v = s / (float)slen[b] + lin_b[0];
    out[b] = 1.f / (1.f + expf(-v));
}

// ---------------- launch -------------------------------------------------------
extern "C" void kernel_launch(void* const* d_in, const int* in_sizes, int n_in,
                              void* d_out, int out_size) {
    const int*   ipts  = (const int*)d_in[0];
    const int*   slen  = (const int*)d_in[1];
    const float* h0    = (const float*)d_in[2];
    const float* c0    = (const float*)d_in[3];
    const float* emb   = (const float*)d_in[4];
    const float* convw = (const float*)d_in[5];
    const float* convb = (const float*)d_in[6];
    const float* w_ih  = (const float*)d_in[7];
    const float* w_hh  = (const float*)d_in[8];
    const float* b_ih  = (const float*)d_in[9];
    const float* b_hh  = (const float*)d_in[10];
    const float* lin_w = (const float*)d_in[11];
    const float* lin_b = (const float*)d_in[12];
    float* out = (float*)d_out;

    float *p_xemb, *p_conv, *p_gx, *p_wT;
    cudaGetSymbolAddress((void**)&p_xemb, g_xemb);
    cudaGetSymbolAddress((void**)&p_conv, g_conv);
    cudaGetSymbolAddress((void**)&p_gx, g_gx);
    cudaGetSymbolAddress((void**)&p_wT, g_wT);

    // 1) embedding gather (bulk blocks, dead rows skipped)
    k_embed<<<(B_ * S_) / 64, 256>>>(ipts, emb, slen);
    // 2) transpose conv weights to [F][768]
    k_wt<<<(3 * E_ * F_ + 255) / 256, 256>>>(convw);
    // 3) conv as tf32-MMA NT GEMM over contiguous 768-float windows (+ skip)
    {
        dim3 g(F_ / 128, (B_ * T_) / 128);  // (2, 511)
        k_gemm<1><<<g, 256>>>(p_xemb, p_wT, p_conv, B_ * T_, F_, 3 * E_, convb, nullptr, slen);
    }
    // 4) input projection via tf32 MMA: gates_x = conv @ w_ih^T + bias (+ skip)
    {
        dim3 g(G_ / 128, (B_ * T_) / 128);  // (8, 511)
        k_gemm<0><<<g, 256>>>(p_conv, w_ih, p_gx, B_ * T_, G_, F_, b_ih, b_hh, slen);
    }
    // 5) cluster LSTM recurrence (W in registers, barrier.cluster, paired stores)
    k_lstm<<<NCLUS * CS, 256>>>(w_hh, h0, c0, slen, lin_w);
    // 6) final: masked mean . linear . sigmoid
    k_final<<<1, 64>>>(slen, lin_b, out);
}